// round 2
// baseline (speedup 1.0000x reference)
#include <cuda_runtime.h>
#include <math.h>
#include <stdint.h>

// Problem constants
#define Bb    4
#define Tt    2048
#define Cc    1024
#define Hh    16
#define HDd   64
#define MROWS (Bb*Tt)      // 8192
#define THREEC (3*Cc)      // 3072

// Scratch (allocation-free rule: __device__ globals)
__device__ float g_qkv[(size_t)MROWS * THREEC];  // ~100 MB
__device__ float g_att[(size_t)MROWS * Cc];      // ~33 MB

// ---------------------------------------------------------------------------
// TF32 tensor-core GEMM:  Out[M,N] = A[M,K] @ B[N,K]^T  (+ bias)
// 3xTF32 split for ~fp32 accuracy. BM=BN=128, BK=32, 256 thr, cp.async pipe.
// ---------------------------------------------------------------------------
#define SMLD   36            // padded row length (floats), 16B-aligned rows
#define SMTILE (128*SMLD)    // one buffer, one operand

__device__ __forceinline__ void tf32_split(float x, uint32_t& hi, uint32_t& lo) {
    asm("cvt.rna.tf32.f32 %0, %1;" : "=r"(hi) : "f"(x));
    float r = x - __uint_as_float(hi);
    asm("cvt.rna.tf32.f32 %0, %1;" : "=r"(lo) : "f"(r));
}

#define MMA_TF32(c, a, b)                                                     \
    asm volatile(                                                             \
        "mma.sync.aligned.m16n8k8.row.col.f32.tf32.tf32.f32 "                 \
        "{%0,%1,%2,%3},{%4,%5,%6,%7},{%8,%9},{%0,%1,%2,%3};"                  \
        : "+f"(c[0]), "+f"(c[1]), "+f"(c[2]), "+f"(c[3])                      \
        : "r"(a[0]), "r"(a[1]), "r"(a[2]), "r"(a[3]), "r"(b[0]), "r"(b[1]))

#define CP_ASYNC16(dst_u32, src_ptr)                                          \
    asm volatile("cp.async.ca.shared.global [%0], [%1], 16;\n"                \
                 :: "r"(dst_u32), "l"(src_ptr) : "memory")

template<bool HAS_BIAS>
__global__ __launch_bounds__(256)
void gemm_tf32(const float* __restrict__ A, const float* __restrict__ B,
               const float* __restrict__ bias, float* __restrict__ Out,
               int M, int N, int K)
{
    extern __shared__ float sm[];
    float* As = sm;                 // [2][128][SMLD]
    float* Bs = sm + 2 * SMTILE;    // [2][128][SMLD]

    const int tid  = threadIdx.x;
    const int warp = tid >> 5;
    const int lane = tid & 31;
    const int wm   = warp & 1;        // 2 warps along M
    const int wn   = warp >> 1;       // 4 warps along N
    const int gid  = lane >> 2;       // 0..7
    const int tg   = lane & 3;        // 0..3

    const int bm = blockIdx.y * 128;
    const int bn = blockIdx.x * 128;

    float c[4][4][4];
    #pragma unroll
    for (int i = 0; i < 4; i++)
        #pragma unroll
        for (int j = 0; j < 4; j++)
            #pragma unroll
            for (int q = 0; q < 4; q++) c[i][j][q] = 0.f;

    // gmem->smem copy mapping: 4 rounds of (32 rows x 32 cols)
    const int lrow = tid >> 3;            // 0..31
    const int lcol = (tid & 7) << 2;      // 0,4,...,28

    const float* agp = A + (size_t)(bm + lrow) * K + lcol;
    const float* bgp = B + (size_t)(bn + lrow) * K + lcol;

    uint32_t as_base = (uint32_t)__cvta_generic_to_shared(As) +
                       (lrow * SMLD + lcol) * 4;
    uint32_t bs_base = (uint32_t)__cvta_generic_to_shared(Bs) +
                       (lrow * SMLD + lcol) * 4;

    const int ntiles = K >> 5;   // K/32

    // prologue: tile 0 -> buf 0
    {
        #pragma unroll
        for (int r = 0; r < 4; r++) {
            CP_ASYNC16(as_base + r * 32 * SMLD * 4, agp + (size_t)(r * 32) * K);
            CP_ASYNC16(bs_base + r * 32 * SMLD * 4, bgp + (size_t)(r * 32) * K);
        }
        asm volatile("cp.async.commit_group;\n" ::: "memory");
    }

    for (int t = 0; t < ntiles; t++) {
        if (t + 1 < ntiles) {
            int buf = (t + 1) & 1;
            int k0  = (t + 1) << 5;
            #pragma unroll
            for (int r = 0; r < 4; r++) {
                CP_ASYNC16(as_base + (buf * SMTILE + r * 32 * SMLD) * 4,
                           agp + (size_t)(r * 32) * K + k0);
                CP_ASYNC16(bs_base + (buf * SMTILE + r * 32 * SMLD) * 4,
                           bgp + (size_t)(r * 32) * K + k0);
            }
            asm volatile("cp.async.commit_group;\n" ::: "memory");
            asm volatile("cp.async.wait_group 1;\n" ::: "memory");
        } else {
            asm volatile("cp.async.wait_group 0;\n" ::: "memory");
        }
        __syncthreads();

        const float* as = As + (t & 1) * SMTILE;
        const float* bs = Bs + (t & 1) * SMTILE;

        #pragma unroll
        for (int kk = 0; kk < 32; kk += 8) {
            uint32_t Ab[4][4], Al[4][4];
            #pragma unroll
            for (int mf = 0; mf < 4; mf++) {
                int m = wm * 64 + mf * 16 + gid;
                float f0 = as[m * SMLD + kk + tg];
                float f1 = as[(m + 8) * SMLD + kk + tg];
                float f2 = as[m * SMLD + kk + tg + 4];
                float f3 = as[(m + 8) * SMLD + kk + tg + 4];
                tf32_split(f0, Ab[mf][0], Al[mf][0]);
                tf32_split(f1, Ab[mf][1], Al[mf][1]);
                tf32_split(f2, Ab[mf][2], Al[mf][2]);
                tf32_split(f3, Ab[mf][3], Al[mf][3]);
            }
            uint32_t Bbf[4][2], Bl[4][2];
            #pragma unroll
            for (int nf = 0; nf < 4; nf++) {
                int n = wn * 32 + nf * 8 + gid;
                float g0 = bs[n * SMLD + kk + tg];
                float g1 = bs[n * SMLD + kk + tg + 4];
                tf32_split(g0, Bbf[nf][0], Bl[nf][0]);
                tf32_split(g1, Bbf[nf][1], Bl[nf][1]);
            }
            #pragma unroll
            for (int mf = 0; mf < 4; mf++)
                #pragma unroll
                for (int nf = 0; nf < 4; nf++) {
                    MMA_TF32(c[mf][nf], Ab[mf], Bbf[nf]);
                    MMA_TF32(c[mf][nf], Ab[mf], Bl[nf]);
                    MMA_TF32(c[mf][nf], Al[mf], Bbf[nf]);
                }
        }
        __syncthreads();
    }

    // epilogue
    #pragma unroll
    for (int mf = 0; mf < 4; mf++) {
        #pragma unroll
        for (int nf = 0; nf < 4; nf++) {
            int row = bm + wm * 64 + mf * 16 + gid;
            int col = bn + wn * 32 + nf * 8 + tg * 2;
            float2 v0, v1;
            v0.x = c[mf][nf][0]; v0.y = c[mf][nf][1];
            v1.x = c[mf][nf][2]; v1.y = c[mf][nf][3];
            if (HAS_BIAS) {
                float2 bv = *(const float2*)&bias[col];
                v0.x += bv.x; v0.y += bv.y;
                v1.x += bv.x; v1.y += bv.y;
            }
            *(float2*)&Out[(size_t)row * N + col] = v0;
            *(float2*)&Out[(size_t)(row + 8) * N + col] = v1;
        }
    }
}

// ---------------------------------------------------------------------------
// Flash attention, fp32 (unchanged from round 1).
// ---------------------------------------------------------------------------
#define LDP 68

__global__ __launch_bounds__(256)
void flash_attn(const float* __restrict__ qkv, float* __restrict__ out)
{
    extern __shared__ float smem[];
    float* Qt   = smem;
    float* Kt   = Qt + 64 * LDP;
    float* Vs   = Kt + 64 * LDP;
    float* Ps   = Vs + 64 * LDP;
    float* sm_m = Ps + 64 * LDP;
    float* sm_l = sm_m + 64;
    float* sm_a = sm_l + 64;

    int bh  = blockIdx.x;
    int qt  = blockIdx.y;
    int b   = bh >> 4;
    int h   = bh & 15;
    int tid = threadIdx.x;
    int tr  = tid >> 4;
    int tc  = tid & 15;

    const float scale = 0.125f;
    const float* base = qkv + (size_t)b * Tt * THREEC + h * (3 * HDd);

    {
        const float* qbase = base + (size_t)(qt * 64) * THREEC;
        #pragma unroll
        for (int r = 0; r < 4; r++) {
            int f   = tid + 256 * r;
            int row = f >> 4;
            int col = (f & 15) << 2;
            float4 v = *(const float4*)(qbase + (size_t)row * THREEC + col);
            Qt[(col + 0) * LDP + row] = v.x * scale;
            Qt[(col + 1) * LDP + row] = v.y * scale;
            Qt[(col + 2) * LDP + row] = v.z * scale;
            Qt[(col + 3) * LDP + row] = v.w * scale;
        }
    }
    if (tid < 64) { sm_m[tid] = -INFINITY; sm_l[tid] = 0.f; }

    float o[4][4];
    #pragma unroll
    for (int i = 0; i < 4; i++)
        #pragma unroll
        for (int j = 0; j < 4; j++) o[i][j] = 0.f;

    __syncthreads();

    for (int kt = 0; kt <= qt; kt++) {
        const float* kbase = base + (size_t)(kt * 64) * THREEC + HDd;
        const float* vbase = kbase + HDd;
        #pragma unroll
        for (int r = 0; r < 4; r++) {
            int f   = tid + 256 * r;
            int row = f >> 4;
            int col = (f & 15) << 2;
            float4 kv = *(const float4*)(kbase + (size_t)row * THREEC + col);
            Kt[(col + 0) * LDP + row] = kv.x;
            Kt[(col + 1) * LDP + row] = kv.y;
            Kt[(col + 2) * LDP + row] = kv.z;
            Kt[(col + 3) * LDP + row] = kv.w;
            float4 vv = *(const float4*)(vbase + (size_t)row * THREEC + col);
            *(float4*)&Vs[row * LDP + col] = vv;
        }
        __syncthreads();

        float s[4][4];
        #pragma unroll
        for (int i = 0; i < 4; i++)
            #pragma unroll
            for (int j = 0; j < 4; j++) s[i][j] = 0.f;

        #pragma unroll 8
        for (int d = 0; d < 64; d++) {
            float4 qv = *(const float4*)&Qt[d * LDP + tr * 4];
            float4 kv = *(const float4*)&Kt[d * LDP + tc * 4];
            float qa[4] = {qv.x, qv.y, qv.z, qv.w};
            float ka[4] = {kv.x, kv.y, kv.z, kv.w};
            #pragma unroll
            for (int i = 0; i < 4; i++)
                #pragma unroll
                for (int j = 0; j < 4; j++)
                    s[i][j] += qa[i] * ka[j];
        }

        if (kt == qt) {
            #pragma unroll
            for (int i = 0; i < 4; i++) {
                int qr = tr * 4 + i;
                #pragma unroll
                for (int j = 0; j < 4; j++) {
                    if (tc * 4 + j > qr) s[i][j] = -INFINITY;
                }
            }
        }

        #pragma unroll
        for (int i = 0; i < 4; i++)
            *(float4*)&Ps[(tr * 4 + i) * LDP + tc * 4] =
                make_float4(s[i][0], s[i][1], s[i][2], s[i][3]);
        __syncthreads();

        if (tid < 64) {
            float mo = sm_m[tid];
            float rmax = mo;
            float* prow = Ps + tid * LDP;
            #pragma unroll 8
            for (int j = 0; j < 64; j++) rmax = fmaxf(rmax, prow[j]);
            float a = __expf(mo - rmax);
            float sum = 0.f;
            #pragma unroll 8
            for (int j = 0; j < 64; j++) {
                float p = __expf(prow[j] - rmax);
                prow[j] = p;
                sum += p;
            }
            sm_l[tid] = sm_l[tid] * a + sum;
            sm_m[tid] = rmax;
            sm_a[tid] = a;
        }
        __syncthreads();

        float ar[4];
        #pragma unroll
        for (int i = 0; i < 4; i++) ar[i] = sm_a[tr * 4 + i];
        #pragma unroll
        for (int i = 0; i < 4; i++)
            #pragma unroll
            for (int j = 0; j < 4; j++) o[i][j] *= ar[i];

        #pragma unroll 4
        for (int kc = 0; kc < 64; kc += 4) {
            float pl[4][4];
            #pragma unroll
            for (int i = 0; i < 4; i++) {
                float4 p4 = *(const float4*)&Ps[(tr * 4 + i) * LDP + kc];
                pl[i][0] = p4.x; pl[i][1] = p4.y; pl[i][2] = p4.z; pl[i][3] = p4.w;
            }
            #pragma unroll
            for (int kk = 0; kk < 4; kk++) {
                float4 vv = *(const float4*)&Vs[(kc + kk) * LDP + tc * 4];
                float va[4] = {vv.x, vv.y, vv.z, vv.w};
                #pragma unroll
                for (int i = 0; i < 4; i++)
                    #pragma unroll
                    for (int j = 0; j < 4; j++)
                        o[i][j] += pl[i][kk] * va[j];
            }
        }
        __syncthreads();
    }

    #pragma unroll
    for (int i = 0; i < 4; i++) {
        float inv = 1.f / sm_l[tr * 4 + i];
        size_t row = (size_t)b * Tt + (size_t)qt * 64 + tr * 4 + i;
        float4 v = make_float4(o[i][0] * inv, o[i][1] * inv,
                               o[i][2] * inv, o[i][3] * inv);
        *(float4*)&out[row * Cc + h * 64 + tc * 4] = v;
    }
}

// ---------------------------------------------------------------------------
extern "C" void kernel_launch(void* const* d_in, const int* in_sizes, int n_in,
                              void* d_out, int out_size)
{
    const float* x     = (const float*)d_in[0];  // [B,T,C]
    const float* Wqkv  = (const float*)d_in[1];  // [3C,C]
    const float* Wproj = (const float*)d_in[2];  // [C,C]
    const float* bproj = (const float*)d_in[3];  // [C]
    float* out = (float*)d_out;                  // [B,T,C]

    float *qkv_p, *att_p;
    cudaGetSymbolAddress((void**)&qkv_p, g_qkv);
    cudaGetSymbolAddress((void**)&att_p, g_att);

    int gemm_smem = 4 * SMTILE * (int)sizeof(float);   // 73728 B
    cudaFuncSetAttribute(gemm_tf32<false>,
                         cudaFuncAttributeMaxDynamicSharedMemorySize, gemm_smem);
    cudaFuncSetAttribute(gemm_tf32<true>,
                         cudaFuncAttributeMaxDynamicSharedMemorySize, gemm_smem);

    // 1) QKV projection (tensor cores, 3xTF32)
    dim3 g1(THREEC / 128, MROWS / 128);
    gemm_tf32<false><<<g1, 256, gemm_smem>>>(x, Wqkv, nullptr, qkv_p,
                                             MROWS, THREEC, Cc);

    // 2) Causal flash attention (fp32)
    int fa_smem = (4 * 64 * LDP + 3 * 64) * (int)sizeof(float);
    cudaFuncSetAttribute(flash_attn, cudaFuncAttributeMaxDynamicSharedMemorySize,
                         fa_smem);
    flash_attn<<<dim3(Bb * Hh, Tt / 64), 256, fa_smem>>>(qkv_p, att_p);

    // 3) Output projection (+bias, tensor cores, 3xTF32)
    dim3 g3(Cc / 128, MROWS / 128);
    gemm_tf32<true><<<g3, 256, gemm_smem>>>(att_p, Wproj, bproj, out,
                                            MROWS, Cc, Cc);
}

// round 4
// speedup vs baseline: 2.0922x; 2.0922x over previous
#include <cuda_runtime.h>
#include <cuda_bf16.h>
#include <math.h>
#include <stdint.h>

// Problem constants
#define Bb    4
#define Tt    2048
#define Cc    1024
#define Hh    16
#define HDd   64
#define MROWS (Bb*Tt)      // 8192
#define THREEC (3*Cc)      // 3072

// Scratch (allocation-free rule: __device__ globals)
__device__ float g_qkv[(size_t)MROWS * THREEC];
__device__ float g_att[(size_t)MROWS * Cc];
__device__ __nv_bfloat16 g_ah[(size_t)MROWS * Cc];   // A hi, row-major
__device__ __nv_bfloat16 g_al[(size_t)MROWS * Cc];   // A lo
__device__ __nv_bfloat16 g_bh[(size_t)THREEC * Cc];  // B hi
__device__ __nv_bfloat16 g_bl[(size_t)THREEC * Cc];  // B lo

__device__ __forceinline__ uint32_t smem_u32(const void* p) {
    return (uint32_t)__cvta_generic_to_shared(p);
}

#define CP16(dst, src)                                                        \
    asm volatile("cp.async.cg.shared.global [%0], [%1], 16;"                  \
                 :: "r"(dst), "l"(src) : "memory")

#define LDSM4(r0, r1, r2, r3, a)                                              \
    asm volatile("ldmatrix.sync.aligned.m8n8.x4.shared.b16 {%0,%1,%2,%3}, [%4];" \
                 : "=r"(r0), "=r"(r1), "=r"(r2), "=r"(r3) : "r"(a))

#define MMA_BF16(c, a, b0, b1)                                                \
    asm volatile(                                                             \
        "mma.sync.aligned.m16n8k16.row.col.f32.bf16.bf16.f32 "                \
        "{%0,%1,%2,%3},{%4,%5,%6,%7},{%8,%9},{%0,%1,%2,%3};"                  \
        : "+f"((c)[0]), "+f"((c)[1]), "+f"((c)[2]), "+f"((c)[3])              \
        : "r"((a)[0]), "r"((a)[1]), "r"((a)[2]), "r"((a)[3]),                 \
          "r"(b0), "r"(b1))

// ---------------------------------------------------------------------------
// Convert fp32 [R,K] row-major -> hi/lo bf16 planes (row-major).
// ---------------------------------------------------------------------------
__global__ __launch_bounds__(256)
void convert_split(const float* __restrict__ X, __nv_bfloat16* __restrict__ Hi,
                   __nv_bfloat16* __restrict__ Lo, int total_pairs)
{
    int e = blockIdx.x * 256 + threadIdx.x;
    if (e >= total_pairs) return;
    float2 v = *(const float2*)(X + (size_t)e * 2);
    __nv_bfloat16 h0 = __float2bfloat16_rn(v.x);
    __nv_bfloat16 l0 = __float2bfloat16_rn(v.x - __bfloat162float(h0));
    __nv_bfloat16 h1 = __float2bfloat16_rn(v.y);
    __nv_bfloat16 l1 = __float2bfloat16_rn(v.y - __bfloat162float(h1));
    uint32_t hp = ((uint32_t)__bfloat16_as_ushort(h1) << 16) | __bfloat16_as_ushort(h0);
    uint32_t lp = ((uint32_t)__bfloat16_as_ushort(l1) << 16) | __bfloat16_as_ushort(l0);
    *(uint32_t*)((char*)Hi + (size_t)e * 4) = hp;
    *(uint32_t*)((char*)Lo + (size_t)e * 4) = lp;
}

// ---------------------------------------------------------------------------
// bf16 split-2 tensor GEMM: Out[M,N] = A[M,K] @ B[N,K]^T (+bias)
// BM=BN=128, BK=64, 2-stage cp.async, ldmatrix frags, 256 threads (4x2 warps).
// smem per stage: 4 operand tiles x 128x64 bf16 (16KB each) = 64KB.
// ---------------------------------------------------------------------------
#define STAGE 65536
#define OPSZ  16384

__device__ __forceinline__ uint32_t swz(int row, int chunk) {
    return (uint32_t)(row * 128 + (((chunk) ^ (row & 7)) << 4));
}

template<bool HAS_BIAS>
__global__ __launch_bounds__(256)
void gemm_bf16(const __nv_bfloat16* __restrict__ Ah,
               const __nv_bfloat16* __restrict__ Al,
               const __nv_bfloat16* __restrict__ Bh,
               const __nv_bfloat16* __restrict__ Bl,
               const float* __restrict__ bias, float* __restrict__ Out,
               int M, int N, int K)
{
    extern __shared__ __align__(128) char sm[];
    const int tid  = threadIdx.x;
    const int warp = tid >> 5;
    const int lane = tid & 31;
    const int wm   = warp & 3;        // 4 warps along M (32 rows each)
    const int wn   = warp >> 2;       // 2 warps along N (64 cols each)
    const int grp  = lane >> 3;
    const int j    = lane & 7;
    const int bm   = blockIdx.y * 128;
    const int bn   = blockIdx.x * 128;

    float c[2][8][4];
    #pragma unroll
    for (int a = 0; a < 2; a++)
        #pragma unroll
        for (int b = 0; b < 8; b++)
            #pragma unroll
            for (int q = 0; q < 4; q++) c[a][b][q] = 0.f;

    // cp.async mapping: 4 operands x 64 threads; 16 chunks of 16B per thread
    const int op    = tid >> 6;        // 0:Ah 1:Al 2:Bh 3:Bl
    const int tid64 = tid & 63;
    const __nv_bfloat16* gptr =
        (op == 0) ? Ah + (size_t)bm * K :
        (op == 1) ? Al + (size_t)bm * K :
        (op == 2) ? Bh + (size_t)bn * K :
                    Bl + (size_t)bn * K;
    const uint32_t smem0 = smem_u32(sm);
    const uint32_t my_op_s = smem0 + op * OPSZ;

    const int NKC = K >> 6;

    // prologue: chunk 0 -> buf 0
    #pragma unroll
    for (int i = 0; i < 16; i++) {
        int ch  = i * 64 + tid64;
        int row = ch >> 3, cc = ch & 7;
        CP16(my_op_s + swz(row, cc), gptr + (size_t)row * K + cc * 8);
    }
    asm volatile("cp.async.commit_group;" ::: "memory");

    for (int t = 0; t < NKC; t++) {
        if (t + 1 < NKC) {
            uint32_t stg = my_op_s + ((t + 1) & 1) * STAGE;
            int k0 = (t + 1) << 6;
            #pragma unroll
            for (int i = 0; i < 16; i++) {
                int ch  = i * 64 + tid64;
                int row = ch >> 3, cc = ch & 7;
                CP16(stg + swz(row, cc), gptr + (size_t)row * K + k0 + cc * 8);
            }
            asm volatile("cp.async.commit_group;" ::: "memory");
            asm volatile("cp.async.wait_group 1;" ::: "memory");
        } else {
            asm volatile("cp.async.wait_group 0;" ::: "memory");
        }
        __syncthreads();

        uint32_t base = smem0 + (t & 1) * STAGE;
        uint32_t sAh = base, sAl = base + OPSZ;
        uint32_t sBh = base + 2 * OPSZ, sBl = base + 3 * OPSZ;

        #pragma unroll
        for (int ks = 0; ks < 4; ks++) {
            int kch = ks << 1;   // k-chunk base (16 elems = 2 chunks of 8)
            uint32_t ah[2][4], al[2][4];
            #pragma unroll
            for (int mt = 0; mt < 2; mt++) {
                int row = wm * 32 + mt * 16 + ((grp & 1) << 3) + j;
                uint32_t off = swz(row, kch + (grp >> 1));
                LDSM4(ah[mt][0], ah[mt][1], ah[mt][2], ah[mt][3], sAh + off);
                LDSM4(al[mt][0], al[mt][1], al[mt][2], al[mt][3], sAl + off);
            }
            #pragma unroll
            for (int nb = 0; nb < 4; nb++) {
                int rowb = wn * 64 + nb * 16 + ((grp >> 1) << 3) + j;
                uint32_t offb = swz(rowb, kch + (grp & 1));
                uint32_t bh[4], bl[4];
                LDSM4(bh[0], bh[1], bh[2], bh[3], sBh + offb);
                LDSM4(bl[0], bl[1], bl[2], bl[3], sBl + offb);
                #pragma unroll
                for (int mt = 0; mt < 2; mt++) {
                    MMA_BF16(c[mt][nb*2],   ah[mt], bh[0], bh[1]);
                    MMA_BF16(c[mt][nb*2],   ah[mt], bl[0], bl[1]);
                    MMA_BF16(c[mt][nb*2],   al[mt], bh[0], bh[1]);
                    MMA_BF16(c[mt][nb*2+1], ah[mt], bh[2], bh[3]);
                    MMA_BF16(c[mt][nb*2+1], ah[mt], bl[2], bl[3]);
                    MMA_BF16(c[mt][nb*2+1], al[mt], bh[2], bh[3]);
                }
            }
        }
        __syncthreads();
    }

    // epilogue: fragment rows lane>>2 and +8, cols (lane&3)*2
    #pragma unroll
    for (int mt = 0; mt < 2; mt++) {
        int r0 = bm + wm * 32 + mt * 16 + (lane >> 2);
        #pragma unroll
        for (int ng = 0; ng < 8; ng++) {
            int col = bn + wn * 64 + ng * 8 + (lane & 3) * 2;
            float2 v0 = make_float2(c[mt][ng][0], c[mt][ng][1]);
            float2 v1 = make_float2(c[mt][ng][2], c[mt][ng][3]);
            if (HAS_BIAS) {
                float2 bv = *(const float2*)&bias[col];
                v0.x += bv.x; v0.y += bv.y;
                v1.x += bv.x; v1.y += bv.y;
            }
            *(float2*)&Out[(size_t)r0 * N + col] = v0;
            *(float2*)&Out[(size_t)(r0 + 8) * N + col] = v1;
        }
    }
}

// ---------------------------------------------------------------------------
// Flash attention, fp32 (unchanged — known good).
// ---------------------------------------------------------------------------
#define LDP 68

__global__ __launch_bounds__(256)
void flash_attn(const float* __restrict__ qkv, float* __restrict__ out)
{
    extern __shared__ float smem[];
    float* Qt   = smem;
    float* Kt   = Qt + 64 * LDP;
    float* Vs   = Kt + 64 * LDP;
    float* Ps   = Vs + 64 * LDP;
    float* sm_m = Ps + 64 * LDP;
    float* sm_l = sm_m + 64;
    float* sm_a = sm_l + 64;

    int bh  = blockIdx.x;
    int qt  = blockIdx.y;
    int b   = bh >> 4;
    int h   = bh & 15;
    int tid = threadIdx.x;
    int tr  = tid >> 4;
    int tc  = tid & 15;

    const float scale = 0.125f;
    const float* base = qkv + (size_t)b * Tt * THREEC + h * (3 * HDd);

    {
        const float* qbase = base + (size_t)(qt * 64) * THREEC;
        #pragma unroll
        for (int r = 0; r < 4; r++) {
            int f   = tid + 256 * r;
            int row = f >> 4;
            int col = (f & 15) << 2;
            float4 v = *(const float4*)(qbase + (size_t)row * THREEC + col);
            Qt[(col + 0) * LDP + row] = v.x * scale;
            Qt[(col + 1) * LDP + row] = v.y * scale;
            Qt[(col + 2) * LDP + row] = v.z * scale;
            Qt[(col + 3) * LDP + row] = v.w * scale;
        }
    }
    if (tid < 64) { sm_m[tid] = -INFINITY; sm_l[tid] = 0.f; }

    float o[4][4];
    #pragma unroll
    for (int i = 0; i < 4; i++)
        #pragma unroll
        for (int j = 0; j < 4; j++) o[i][j] = 0.f;

    __syncthreads();

    for (int kt = 0; kt <= qt; kt++) {
        const float* kbase = base + (size_t)(kt * 64) * THREEC + HDd;
        const float* vbase = kbase + HDd;
        #pragma unroll
        for (int r = 0; r < 4; r++) {
            int f   = tid + 256 * r;
            int row = f >> 4;
            int col = (f & 15) << 2;
            float4 kv = *(const float4*)(kbase + (size_t)row * THREEC + col);
            Kt[(col + 0) * LDP + row] = kv.x;
            Kt[(col + 1) * LDP + row] = kv.y;
            Kt[(col + 2) * LDP + row] = kv.z;
            Kt[(col + 3) * LDP + row] = kv.w;
            float4 vv = *(const float4*)(vbase + (size_t)row * THREEC + col);
            *(float4*)&Vs[row * LDP + col] = vv;
        }
        __syncthreads();

        float s[4][4];
        #pragma unroll
        for (int i = 0; i < 4; i++)
            #pragma unroll
            for (int j = 0; j < 4; j++) s[i][j] = 0.f;

        #pragma unroll 8
        for (int d = 0; d < 64; d++) {
            float4 qv = *(const float4*)&Qt[d * LDP + tr * 4];
            float4 kv = *(const float4*)&Kt[d * LDP + tc * 4];
            float qa[4] = {qv.x, qv.y, qv.z, qv.w};
            float ka[4] = {kv.x, kv.y, kv.z, kv.w};
            #pragma unroll
            for (int i = 0; i < 4; i++)
                #pragma unroll
                for (int j = 0; j < 4; j++)
                    s[i][j] += qa[i] * ka[j];
        }

        if (kt == qt) {
            #pragma unroll
            for (int i = 0; i < 4; i++) {
                int qr = tr * 4 + i;
                #pragma unroll
                for (int j = 0; j < 4; j++) {
                    if (tc * 4 + j > qr) s[i][j] = -INFINITY;
                }
            }
        }

        #pragma unroll
        for (int i = 0; i < 4; i++)
            *(float4*)&Ps[(tr * 4 + i) * LDP + tc * 4] =
                make_float4(s[i][0], s[i][1], s[i][2], s[i][3]);
        __syncthreads();

        if (tid < 64) {
            float mo = sm_m[tid];
            float rmax = mo;
            float* prow = Ps + tid * LDP;
            #pragma unroll 8
            for (int j = 0; j < 64; j++) rmax = fmaxf(rmax, prow[j]);
            float a = __expf(mo - rmax);
            float sum = 0.f;
            #pragma unroll 8
            for (int j = 0; j < 64; j++) {
                float p = __expf(prow[j] - rmax);
                prow[j] = p;
                sum += p;
            }
            sm_l[tid] = sm_l[tid] * a + sum;
            sm_m[tid] = rmax;
            sm_a[tid] = a;
        }
        __syncthreads();

        float ar[4];
        #pragma unroll
        for (int i = 0; i < 4; i++) ar[i] = sm_a[tr * 4 + i];
        #pragma unroll
        for (int i = 0; i < 4; i++)
            #pragma unroll
            for (int j = 0; j < 4; j++) o[i][j] *= ar[i];

        #pragma unroll 4
        for (int kc = 0; kc < 64; kc += 4) {
            float pl[4][4];
            #pragma unroll
            for (int i = 0; i < 4; i++) {
                float4 p4 = *(const float4*)&Ps[(tr * 4 + i) * LDP + kc];
                pl[i][0] = p4.x; pl[i][1] = p4.y; pl[i][2] = p4.z; pl[i][3] = p4.w;
            }
            #pragma unroll
            for (int kk = 0; kk < 4; kk++) {
                float4 vv = *(const float4*)&Vs[(kc + kk) * LDP + tc * 4];
                float va[4] = {vv.x, vv.y, vv.z, vv.w};
                #pragma unroll
                for (int i = 0; i < 4; i++)
                    #pragma unroll
                    for (int j = 0; j < 4; j++)
                        o[i][j] += pl[i][kk] * va[j];
            }
        }
        __syncthreads();
    }

    #pragma unroll
    for (int i = 0; i < 4; i++) {
        float inv = 1.f / sm_l[tr * 4 + i];
        size_t row = (size_t)b * Tt + (size_t)qt * 64 + tr * 4 + i;
        float4 v = make_float4(o[i][0] * inv, o[i][1] * inv,
                               o[i][2] * inv, o[i][3] * inv);
        *(float4*)&out[row * Cc + h * 64 + tc * 4] = v;
    }
}

// ---------------------------------------------------------------------------
extern "C" void kernel_launch(void* const* d_in, const int* in_sizes, int n_in,
                              void* d_out, int out_size)
{
    const float* x     = (const float*)d_in[0];
    const float* Wqkv  = (const float*)d_in[1];
    const float* Wproj = (const float*)d_in[2];
    const float* bproj = (const float*)d_in[3];
    float* out = (float*)d_out;

    float *qkv_p, *att_p;
    __nv_bfloat16 *ah, *al, *bh, *bl;
    cudaGetSymbolAddress((void**)&qkv_p, g_qkv);
    cudaGetSymbolAddress((void**)&att_p, g_att);
    cudaGetSymbolAddress((void**)&ah, g_ah);
    cudaGetSymbolAddress((void**)&al, g_al);
    cudaGetSymbolAddress((void**)&bh, g_bh);
    cudaGetSymbolAddress((void**)&bl, g_bl);

    const int GEMM_SMEM = 2 * STAGE;  // 128 KB
    cudaFuncSetAttribute(gemm_bf16<false>,
                         cudaFuncAttributeMaxDynamicSharedMemorySize, GEMM_SMEM);
    cudaFuncSetAttribute(gemm_bf16<true>,
                         cudaFuncAttributeMaxDynamicSharedMemorySize, GEMM_SMEM);

    // 1) split-convert x and Wqkv
    convert_split<<<(MROWS * Cc / 2 + 255) / 256, 256>>>(x, ah, al, MROWS * Cc / 2);
    convert_split<<<(THREEC * Cc / 2 + 255) / 256, 256>>>(Wqkv, bh, bl, THREEC * Cc / 2);

    // 2) QKV projection (bf16 split tensor GEMM)
    gemm_bf16<false><<<dim3(THREEC / 128, MROWS / 128), 256, GEMM_SMEM>>>(
        ah, al, bh, bl, nullptr, qkv_p, MROWS, THREEC, Cc);

    // 3) Causal flash attention (fp32)
    int fa_smem = (4 * 64 * LDP + 3 * 64) * (int)sizeof(float);
    cudaFuncSetAttribute(flash_attn, cudaFuncAttributeMaxDynamicSharedMemorySize,
                         fa_smem);
    flash_attn<<<dim3(Bb * Hh, Tt / 64), 256, fa_smem>>>(qkv_p, att_p);

    // 4) split-convert attention output and Wproj
    convert_split<<<(MROWS * Cc / 2 + 255) / 256, 256>>>(att_p, ah, al, MROWS * Cc / 2);
    convert_split<<<(Cc * Cc / 2 + 255) / 256, 256>>>(Wproj, bh, bl, Cc * Cc / 2);

    // 5) Output projection (+bias)
    gemm_bf16<true><<<dim3(Cc / 128, MROWS / 128), 256, GEMM_SMEM>>>(
        ah, al, bh, bl, bproj, out, MROWS, Cc, Cc);
}

// round 5
// speedup vs baseline: 4.0251x; 1.9239x over previous
#include <cuda_runtime.h>
#include <cuda_bf16.h>
#include <math.h>
#include <stdint.h>

// Problem constants
#define Bb    4
#define Tt    2048
#define Cc    1024
#define Hh    16
#define HDd   64
#define MROWS (Bb*Tt)      // 8192
#define THREEC (3*Cc)      // 3072
#define BH    (Bb*Hh)      // 64

// Scratch (allocation-free rule: __device__ globals)
__device__ __nv_bfloat16 g_ah[(size_t)MROWS * Cc];
__device__ __nv_bfloat16 g_al[(size_t)MROWS * Cc];
__device__ __nv_bfloat16 g_bh[(size_t)THREEC * Cc];
__device__ __nv_bfloat16 g_bl[(size_t)THREEC * Cc];
__device__ __nv_bfloat16 g_qh[(size_t)BH * Tt * HDd];
__device__ __nv_bfloat16 g_ql[(size_t)BH * Tt * HDd];
__device__ __nv_bfloat16 g_kh[(size_t)BH * Tt * HDd];
__device__ __nv_bfloat16 g_kl[(size_t)BH * Tt * HDd];
__device__ __nv_bfloat16 g_vh[(size_t)BH * Tt * HDd];
__device__ __nv_bfloat16 g_vl[(size_t)BH * Tt * HDd];

__device__ __forceinline__ uint32_t smem_u32(const void* p) {
    return (uint32_t)__cvta_generic_to_shared(p);
}

#define CP16(dst, src)                                                        \
    asm volatile("cp.async.cg.shared.global [%0], [%1], 16;"                  \
                 :: "r"(dst), "l"(src) : "memory")
#define CP_COMMIT() asm volatile("cp.async.commit_group;" ::: "memory")
#define CP_WAIT(n)  asm volatile("cp.async.wait_group %0;" :: "n"(n) : "memory")

#define LDSM4(r0, r1, r2, r3, a)                                              \
    asm volatile("ldmatrix.sync.aligned.m8n8.x4.shared.b16 {%0,%1,%2,%3}, [%4];" \
                 : "=r"(r0), "=r"(r1), "=r"(r2), "=r"(r3) : "r"(a))
#define LDSM4T(r0, r1, r2, r3, a)                                             \
    asm volatile("ldmatrix.sync.aligned.m8n8.x4.trans.shared.b16 {%0,%1,%2,%3}, [%4];" \
                 : "=r"(r0), "=r"(r1), "=r"(r2), "=r"(r3) : "r"(a))

#define MMA_BF16(c, a, b0, b1)                                                \
    asm volatile(                                                             \
        "mma.sync.aligned.m16n8k16.row.col.f32.bf16.bf16.f32 "                \
        "{%0,%1,%2,%3},{%4,%5,%6,%7},{%8,%9},{%0,%1,%2,%3};"                  \
        : "+f"((c)[0]), "+f"((c)[1]), "+f"((c)[2]), "+f"((c)[3])              \
        : "r"((a)[0]), "r"((a)[1]), "r"((a)[2]), "r"((a)[3]),                 \
          "r"(b0), "r"(b1))

__device__ __forceinline__ uint32_t swz(int row, int chunk) {
    return (uint32_t)(row * 128 + (((chunk) ^ (row & 7)) << 4));
}
__device__ __forceinline__ void split_pack(float a, float b,
                                           uint32_t& hi, uint32_t& lo) {
    __nv_bfloat16 ha = __float2bfloat16_rn(a);
    __nv_bfloat16 hb = __float2bfloat16_rn(b);
    __nv_bfloat16 la = __float2bfloat16_rn(a - __bfloat162float(ha));
    __nv_bfloat16 lb = __float2bfloat16_rn(b - __bfloat162float(hb));
    hi = ((uint32_t)__bfloat16_as_ushort(hb) << 16) | __bfloat16_as_ushort(ha);
    lo = ((uint32_t)__bfloat16_as_ushort(lb) << 16) | __bfloat16_as_ushort(la);
}
__device__ __forceinline__ void store_pair(__nv_bfloat16* Hp, __nv_bfloat16* Lp,
                                           size_t idx, float v0, float v1) {
    __nv_bfloat16 h0 = __float2bfloat16_rn(v0);
    __nv_bfloat16 h1 = __float2bfloat16_rn(v1);
    ushort2 uh = make_ushort2(__bfloat16_as_ushort(h0), __bfloat16_as_ushort(h1));
    *(ushort2*)&Hp[idx] = uh;
    __nv_bfloat16 l0 = __float2bfloat16_rn(v0 - __bfloat162float(h0));
    __nv_bfloat16 l1 = __float2bfloat16_rn(v1 - __bfloat162float(h1));
    ushort2 ul = make_ushort2(__bfloat16_as_ushort(l0), __bfloat16_as_ushort(l1));
    *(ushort2*)&Lp[idx] = ul;
}

// ---------------------------------------------------------------------------
// Convert fp32 -> hi/lo bf16 planes (row-major).
// ---------------------------------------------------------------------------
__global__ __launch_bounds__(256)
void convert_split(const float* __restrict__ X, __nv_bfloat16* __restrict__ Hi,
                   __nv_bfloat16* __restrict__ Lo, int total_pairs)
{
    int e = blockIdx.x * 256 + threadIdx.x;
    if (e >= total_pairs) return;
    float2 v = *(const float2*)(X + (size_t)e * 2);
    __nv_bfloat16 h0 = __float2bfloat16_rn(v.x);
    __nv_bfloat16 l0 = __float2bfloat16_rn(v.x - __bfloat162float(h0));
    __nv_bfloat16 h1 = __float2bfloat16_rn(v.y);
    __nv_bfloat16 l1 = __float2bfloat16_rn(v.y - __bfloat162float(h1));
    uint32_t hp = ((uint32_t)__bfloat16_as_ushort(h1) << 16) | __bfloat16_as_ushort(h0);
    uint32_t lp = ((uint32_t)__bfloat16_as_ushort(l1) << 16) | __bfloat16_as_ushort(l0);
    *(uint32_t*)((char*)Hi + (size_t)e * 4) = hp;
    *(uint32_t*)((char*)Lo + (size_t)e * 4) = lp;
}

// ---------------------------------------------------------------------------
// bf16 split-2 tensor GEMM (mainloop validated in round 4).
// QKV=false: Out fp32 (+bias).  QKV=true: scatter q/k/v hi/lo planes.
// ---------------------------------------------------------------------------
#define STAGE 65536
#define OPSZ  16384

template<bool QKV, bool HAS_BIAS>
__global__ __launch_bounds__(256)
void gemm_bf16(const __nv_bfloat16* __restrict__ Ah,
               const __nv_bfloat16* __restrict__ Al,
               const __nv_bfloat16* __restrict__ Bh,
               const __nv_bfloat16* __restrict__ Bl,
               const float* __restrict__ bias, float* __restrict__ Out,
               __nv_bfloat16* Qh, __nv_bfloat16* Ql,
               __nv_bfloat16* Kh, __nv_bfloat16* Kl,
               __nv_bfloat16* Vh, __nv_bfloat16* Vl,
               int M, int N, int K)
{
    extern __shared__ __align__(128) char sm[];
    const int tid  = threadIdx.x;
    const int warp = tid >> 5;
    const int lane = tid & 31;
    const int wm   = warp & 3;
    const int wn   = warp >> 2;
    const int grp  = lane >> 3;
    const int j    = lane & 7;
    const int bm   = blockIdx.y * 128;
    const int bn   = blockIdx.x * 128;

    float c[2][8][4];
    #pragma unroll
    for (int a = 0; a < 2; a++)
        #pragma unroll
        for (int b = 0; b < 8; b++)
            #pragma unroll
            for (int q = 0; q < 4; q++) c[a][b][q] = 0.f;

    const int op    = tid >> 6;
    const int tid64 = tid & 63;
    const __nv_bfloat16* gptr =
        (op == 0) ? Ah + (size_t)bm * K :
        (op == 1) ? Al + (size_t)bm * K :
        (op == 2) ? Bh + (size_t)bn * K :
                    Bl + (size_t)bn * K;
    const uint32_t smem0 = smem_u32(sm);
    const uint32_t my_op_s = smem0 + op * OPSZ;
    const int NKC = K >> 6;

    #pragma unroll
    for (int i = 0; i < 16; i++) {
        int ch  = i * 64 + tid64;
        int row = ch >> 3, cc = ch & 7;
        CP16(my_op_s + swz(row, cc), gptr + (size_t)row * K + cc * 8);
    }
    CP_COMMIT();

    for (int t = 0; t < NKC; t++) {
        if (t + 1 < NKC) {
            uint32_t stg = my_op_s + ((t + 1) & 1) * STAGE;
            int k0 = (t + 1) << 6;
            #pragma unroll
            for (int i = 0; i < 16; i++) {
                int ch  = i * 64 + tid64;
                int row = ch >> 3, cc = ch & 7;
                CP16(stg + swz(row, cc), gptr + (size_t)row * K + k0 + cc * 8);
            }
            CP_COMMIT();
            CP_WAIT(1);
        } else {
            CP_WAIT(0);
        }
        __syncthreads();

        uint32_t base = smem0 + (t & 1) * STAGE;
        uint32_t sAh = base, sAl = base + OPSZ;
        uint32_t sBh = base + 2 * OPSZ, sBl = base + 3 * OPSZ;

        #pragma unroll
        for (int ks = 0; ks < 4; ks++) {
            int kch = ks << 1;
            uint32_t ah[2][4], al[2][4];
            #pragma unroll
            for (int mt = 0; mt < 2; mt++) {
                int row = wm * 32 + mt * 16 + ((grp & 1) << 3) + j;
                uint32_t off = swz(row, kch + (grp >> 1));
                LDSM4(ah[mt][0], ah[mt][1], ah[mt][2], ah[mt][3], sAh + off);
                LDSM4(al[mt][0], al[mt][1], al[mt][2], al[mt][3], sAl + off);
            }
            #pragma unroll
            for (int nb = 0; nb < 4; nb++) {
                int rowb = wn * 64 + nb * 16 + ((grp >> 1) << 3) + j;
                uint32_t offb = swz(rowb, kch + (grp & 1));
                uint32_t bh[4], bl[4];
                LDSM4(bh[0], bh[1], bh[2], bh[3], sBh + offb);
                LDSM4(bl[0], bl[1], bl[2], bl[3], sBl + offb);
                #pragma unroll
                for (int mt = 0; mt < 2; mt++) {
                    MMA_BF16(c[mt][nb*2],   ah[mt], bh[0], bh[1]);
                    MMA_BF16(c[mt][nb*2],   ah[mt], bl[0], bl[1]);
                    MMA_BF16(c[mt][nb*2],   al[mt], bh[0], bh[1]);
                    MMA_BF16(c[mt][nb*2+1], ah[mt], bh[2], bh[3]);
                    MMA_BF16(c[mt][nb*2+1], ah[mt], bl[2], bl[3]);
                    MMA_BF16(c[mt][nb*2+1], al[mt], bh[2], bh[3]);
                }
            }
        }
        __syncthreads();
    }

    #pragma unroll
    for (int mt = 0; mt < 2; mt++) {
        int r0 = bm + wm * 32 + mt * 16 + (lane >> 2);
        #pragma unroll
        for (int ng = 0; ng < 8; ng++) {
            int col = bn + wn * 64 + ng * 8 + (lane & 3) * 2;
            if (!QKV) {
                float2 v0 = make_float2(c[mt][ng][0], c[mt][ng][1]);
                float2 v1 = make_float2(c[mt][ng][2], c[mt][ng][3]);
                if (HAS_BIAS) {
                    float2 bv = *(const float2*)&bias[col];
                    v0.x += bv.x; v0.y += bv.y;
                    v1.x += bv.x; v1.y += bv.y;
                }
                *(float2*)&Out[(size_t)r0 * N + col] = v0;
                *(float2*)&Out[(size_t)(r0 + 8) * N + col] = v1;
            } else {
                int h  = col / 192;
                int wc = col - h * 192;
                int ty = wc >> 6;
                int d  = wc & 63;
                __nv_bfloat16* Hp = (ty == 0) ? Qh : (ty == 1) ? Kh : Vh;
                __nv_bfloat16* Lp = (ty == 0) ? Ql : (ty == 1) ? Kl : Vl;
                float sc = (ty == 0) ? 0.125f : 1.0f;
                #pragma unroll
                for (int half = 0; half < 2; half++) {
                    int tg2 = r0 + half * 8;
                    size_t idx = (((size_t)((tg2 >> 11) * Hh + h)) * Tt
                                  + (tg2 & 2047)) * HDd + d;
                    store_pair(Hp, Lp, idx,
                               c[mt][ng][half*2] * sc, c[mt][ng][half*2+1] * sc);
                }
            }
        }
    }
}

// ---------------------------------------------------------------------------
// Tensor-core causal flash attention. Bq=64 (4 warps x m16), Bk=64.
// Split-2 bf16 for QK^T and PV. Writes O as hi/lo bf16 planes (proj A input).
// ---------------------------------------------------------------------------
#define FA_SMEM (16384 + 2*32768)   // Q(16K) + 2 KV stages (32K each)

__global__ __launch_bounds__(128)
void flash_attn_tc(const __nv_bfloat16* __restrict__ qh, const __nv_bfloat16* __restrict__ ql,
                   const __nv_bfloat16* __restrict__ kh, const __nv_bfloat16* __restrict__ kl,
                   const __nv_bfloat16* __restrict__ vh, const __nv_bfloat16* __restrict__ vl,
                   __nv_bfloat16* __restrict__ Oh, __nv_bfloat16* __restrict__ Ol)
{
    extern __shared__ __align__(128) char sm[];
    const uint32_t s0  = smem_u32(sm);
    const uint32_t sQh = s0, sQl = s0 + 8192;

    const int bh = blockIdx.x;
    const int qt = (gridDim.y - 1) - blockIdx.y;   // heavy tiles first
    const int tid = threadIdx.x, w = tid >> 5, lane = tid & 31;
    const int g = lane >> 2, tg = lane & 3;
    const int grp = lane >> 3, j = lane & 7;

    const size_t pb = (size_t)bh * Tt * HDd;

    // ---- load Q tile (hi+lo), 128 threads
    {
        int p = tid >> 6, within = tid & 63;
        const __nv_bfloat16* src = (p ? ql : qh) + pb + (size_t)(qt * 64) * HDd;
        uint32_t dst = p ? sQl : sQh;
        #pragma unroll
        for (int i = 0; i < 8; i++) {
            int ch = i * 64 + within;
            CP16(dst + swz(ch >> 3, ch & 7), src + ch * 8);
        }
        CP_COMMIT();
    }
    // ---- prefetch KV tile 0 (warp w loads plane w)
    {
        const __nv_bfloat16* src =
            ((w == 0) ? kh : (w == 1) ? kl : (w == 2) ? vh : vl) + pb;
        uint32_t dst = s0 + 16384 + w * 8192;
        #pragma unroll
        for (int i = 0; i < 16; i++) {
            int ch = i * 32 + lane;
            CP16(dst + swz(ch >> 3, ch & 7), src + ch * 8);
        }
        CP_COMMIT();
    }
    CP_WAIT(1);            // Q done
    __syncthreads();

    // ---- Q fragments register-resident (validated a-frag pattern)
    uint32_t qhf[4][4], qlf[4][4];
    #pragma unroll
    for (int kb = 0; kb < 4; kb++) {
        int row = w * 16 + ((grp & 1) << 3) + j;
        uint32_t off = swz(row, kb * 2 + (grp >> 1));
        LDSM4(qhf[kb][0], qhf[kb][1], qhf[kb][2], qhf[kb][3], sQh + off);
        LDSM4(qlf[kb][0], qlf[kb][1], qlf[kb][2], qlf[kb][3], sQl + off);
    }

    float o[8][4];
    #pragma unroll
    for (int nb = 0; nb < 8; nb++)
        #pragma unroll
        for (int e = 0; e < 4; e++) o[nb][e] = 0.f;
    float mA = -INFINITY, mB = -INFINITY, lA = 0.f, lB = 0.f;

    for (int kt = 0; kt <= qt; kt++) {
        if (kt < qt) {      // prefetch next stage
            const __nv_bfloat16* src =
                ((w == 0) ? kh : (w == 1) ? kl : (w == 2) ? vh : vl)
                + pb + (size_t)((kt + 1) * 64) * HDd;
            uint32_t dst = s0 + 16384 + ((kt + 1) & 1) * 32768 + w * 8192;
            #pragma unroll
            for (int i = 0; i < 16; i++) {
                int ch = i * 32 + lane;
                CP16(dst + swz(ch >> 3, ch & 7), src + ch * 8);
            }
            CP_COMMIT();
            CP_WAIT(1);
        } else {
            CP_WAIT(0);
        }
        __syncthreads();

        uint32_t kbse = s0 + 16384 + (kt & 1) * 32768;
        uint32_t sKh = kbse, sKl = kbse + 8192;
        uint32_t sVh = kbse + 16384, sVl = kbse + 24576;

        // ---- S = Q K^T (split-2: 3 products)
        float s[8][4];
        #pragma unroll
        for (int nb = 0; nb < 8; nb++)
            #pragma unroll
            for (int e = 0; e < 4; e++) s[nb][e] = 0.f;

        #pragma unroll
        for (int kb = 0; kb < 4; kb++) {
            #pragma unroll
            for (int p = 0; p < 4; p++) {
                int rowb = p * 16 + ((grp >> 1) << 3) + j;
                uint32_t off = swz(rowb, kb * 2 + (grp & 1));
                uint32_t bhr[4], blr[4];
                LDSM4(bhr[0], bhr[1], bhr[2], bhr[3], sKh + off);
                LDSM4(blr[0], blr[1], blr[2], blr[3], sKl + off);
                MMA_BF16(s[p*2],   qhf[kb], bhr[0], bhr[1]);
                MMA_BF16(s[p*2],   qhf[kb], blr[0], blr[1]);
                MMA_BF16(s[p*2],   qlf[kb], bhr[0], bhr[1]);
                MMA_BF16(s[p*2+1], qhf[kb], bhr[2], bhr[3]);
                MMA_BF16(s[p*2+1], qhf[kb], blr[2], blr[3]);
                MMA_BF16(s[p*2+1], qlf[kb], bhr[2], bhr[3]);
            }
        }

        // ---- causal mask on diagonal tile
        if (kt == qt) {
            int rowA = w * 16 + g, rowB = rowA + 8;
            #pragma unroll
            for (int nb = 0; nb < 8; nb++) {
                int c0 = nb * 8 + tg * 2;
                if (c0 > rowA)     s[nb][0] = -INFINITY;
                if (c0 + 1 > rowA) s[nb][1] = -INFINITY;
                if (c0 > rowB)     s[nb][2] = -INFINITY;
                if (c0 + 1 > rowB) s[nb][3] = -INFINITY;
            }
        }

        // ---- online softmax (rows A = w*16+g, B = +8)
        float mxA = -INFINITY, mxB = -INFINITY;
        #pragma unroll
        for (int nb = 0; nb < 8; nb++) {
            mxA = fmaxf(mxA, fmaxf(s[nb][0], s[nb][1]));
            mxB = fmaxf(mxB, fmaxf(s[nb][2], s[nb][3]));
        }
        #pragma unroll
        for (int d = 1; d < 4; d <<= 1) {
            mxA = fmaxf(mxA, __shfl_xor_sync(0xffffffffu, mxA, d));
            mxB = fmaxf(mxB, __shfl_xor_sync(0xffffffffu, mxB, d));
        }
        float mAn = fmaxf(mA, mxA), mBn = fmaxf(mB, mxB);
        float aA = __expf(mA - mAn), aB = __expf(mB - mBn);
        float sumA = 0.f, sumB = 0.f;
        #pragma unroll
        for (int nb = 0; nb < 8; nb++) {
            s[nb][0] = __expf(s[nb][0] - mAn); sumA += s[nb][0];
            s[nb][1] = __expf(s[nb][1] - mAn); sumA += s[nb][1];
            s[nb][2] = __expf(s[nb][2] - mBn); sumB += s[nb][2];
            s[nb][3] = __expf(s[nb][3] - mBn); sumB += s[nb][3];
        }
        #pragma unroll
        for (int d = 1; d < 4; d <<= 1) {
            sumA += __shfl_xor_sync(0xffffffffu, sumA, d);
            sumB += __shfl_xor_sync(0xffffffffu, sumB, d);
        }
        lA = lA * aA + sumA; lB = lB * aB + sumB;
        mA = mAn; mB = mBn;
        #pragma unroll
        for (int nb = 0; nb < 8; nb++) {
            o[nb][0] *= aA; o[nb][1] *= aA;
            o[nb][2] *= aB; o[nb][3] *= aB;
        }

        // ---- O += P V (split-2: 3 products), V via ldmatrix.trans
        #pragma unroll
        for (int kb = 0; kb < 4; kb++) {
            uint32_t ph[4], pl[4];
            split_pack(s[2*kb][0],   s[2*kb][1],   ph[0], pl[0]);
            split_pack(s[2*kb][2],   s[2*kb][3],   ph[1], pl[1]);
            split_pack(s[2*kb+1][0], s[2*kb+1][1], ph[2], pl[2]);
            split_pack(s[2*kb+1][2], s[2*kb+1][3], ph[3], pl[3]);
            #pragma unroll
            for (int p = 0; p < 4; p++) {
                int keyrow = kb * 16 + ((grp & 1) << 3) + j;
                uint32_t off = swz(keyrow, p * 2 + (grp >> 1));
                uint32_t vhr[4], vlr[4];
                LDSM4T(vhr[0], vhr[1], vhr[2], vhr[3], sVh + off);
                LDSM4T(vlr[0], vlr[1], vlr[2], vlr[3], sVl + off);
                MMA_BF16(o[p*2],   ph, vhr[0], vhr[1]);
                MMA_BF16(o[p*2],   ph, vlr[0], vlr[1]);
                MMA_BF16(o[p*2],   pl, vhr[0], vhr[1]);
                MMA_BF16(o[p*2+1], ph, vhr[2], vhr[3]);
                MMA_BF16(o[p*2+1], ph, vlr[2], vlr[3]);
                MMA_BF16(o[p*2+1], pl, vhr[2], vhr[3]);
            }
        }
        __syncthreads();
    }

    // ---- normalize + store O hi/lo into proj A planes [t][C]
    float invA = 1.f / lA, invB = 1.f / lB;
    int b = bh >> 4, h = bh & 15;
    int tA = b * Tt + qt * 64 + w * 16 + g;
    #pragma unroll
    for (int nb = 0; nb < 8; nb++) {
        int col = h * 64 + nb * 8 + tg * 2;
        store_pair(Oh, Ol, (size_t)tA * Cc + col, o[nb][0]*invA, o[nb][1]*invA);
        store_pair(Oh, Ol, (size_t)(tA + 8) * Cc + col, o[nb][2]*invB, o[nb][3]*invB);
    }
}

// ---------------------------------------------------------------------------
extern "C" void kernel_launch(void* const* d_in, const int* in_sizes, int n_in,
                              void* d_out, int out_size)
{
    const float* x     = (const float*)d_in[0];
    const float* Wqkv  = (const float*)d_in[1];
    const float* Wproj = (const float*)d_in[2];
    const float* bproj = (const float*)d_in[3];
    float* out = (float*)d_out;

    __nv_bfloat16 *ah, *al, *bh, *bl, *qh, *ql, *kh, *kl, *vh, *vl;
    cudaGetSymbolAddress((void**)&ah, g_ah);
    cudaGetSymbolAddress((void**)&al, g_al);
    cudaGetSymbolAddress((void**)&bh, g_bh);
    cudaGetSymbolAddress((void**)&bl, g_bl);
    cudaGetSymbolAddress((void**)&qh, g_qh);
    cudaGetSymbolAddress((void**)&ql, g_ql);
    cudaGetSymbolAddress((void**)&kh, g_kh);
    cudaGetSymbolAddress((void**)&kl, g_kl);
    cudaGetSymbolAddress((void**)&vh, g_vh);
    cudaGetSymbolAddress((void**)&vl, g_vl);

    const int GEMM_SMEM = 2 * STAGE;  // 128 KB
    cudaFuncSetAttribute((const void*)gemm_bf16<true, false>,
                         cudaFuncAttributeMaxDynamicSharedMemorySize, GEMM_SMEM);
    cudaFuncSetAttribute((const void*)gemm_bf16<false, true>,
                         cudaFuncAttributeMaxDynamicSharedMemorySize, GEMM_SMEM);
    cudaFuncSetAttribute((const void*)flash_attn_tc,
                         cudaFuncAttributeMaxDynamicSharedMemorySize, FA_SMEM);

    // 1) split-convert x and Wqkv
    convert_split<<<(MROWS * Cc / 2 + 255) / 256, 256>>>(x, ah, al, MROWS * Cc / 2);
    convert_split<<<(THREEC * Cc / 2 + 255) / 256, 256>>>(Wqkv, bh, bl, THREEC * Cc / 2);

    // 2) QKV projection -> q/k/v hi/lo planes (q pre-scaled)
    gemm_bf16<true, false><<<dim3(THREEC / 128, MROWS / 128), 256, GEMM_SMEM>>>(
        ah, al, bh, bl, nullptr, nullptr, qh, ql, kh, kl, vh, vl,
        MROWS, THREEC, Cc);

    // 3) Tensor-core causal flash attention -> proj A planes
    flash_attn_tc<<<dim3(BH, Tt / 64), 128, FA_SMEM>>>(
        qh, ql, kh, kl, vh, vl, ah, al);

    // 4) split-convert Wproj
    convert_split<<<(Cc * Cc / 2 + 255) / 256, 256>>>(Wproj, bh, bl, Cc * Cc / 2);

    // 5) Output projection (+bias)
    gemm_bf16<false, true><<<dim3(Cc / 128, MROWS / 128), 256, GEMM_SMEM>>>(
        ah, al, bh, bl, bproj, out, nullptr, nullptr, nullptr, nullptr,
        nullptr, nullptr, MROWS, Cc, Cc);
}

// round 6
// speedup vs baseline: 4.0679x; 1.0107x over previous
#include <cuda_runtime.h>
#include <cuda_bf16.h>
#include <math.h>
#include <stdint.h>

// Problem constants
#define Bb    4
#define Tt    2048
#define Cc    1024
#define Hh    16
#define HDd   64
#define MROWS (Bb*Tt)      // 8192
#define THREEC (3*Cc)      // 3072
#define BH    (Bb*Hh)      // 64

// Scratch (allocation-free rule: __device__ globals)
__device__ __nv_bfloat16 g_ah[(size_t)MROWS * Cc];
__device__ __nv_bfloat16 g_al[(size_t)MROWS * Cc];
__device__ __nv_bfloat16 g_bh[(size_t)THREEC * Cc];
__device__ __nv_bfloat16 g_bl[(size_t)THREEC * Cc];
__device__ __nv_bfloat16 g_qh[(size_t)BH * Tt * HDd];
__device__ __nv_bfloat16 g_ql[(size_t)BH * Tt * HDd];
__device__ __nv_bfloat16 g_kh[(size_t)BH * Tt * HDd];
__device__ __nv_bfloat16 g_kl[(size_t)BH * Tt * HDd];
__device__ __nv_bfloat16 g_vh[(size_t)BH * Tt * HDd];
__device__ __nv_bfloat16 g_vl[(size_t)BH * Tt * HDd];

__device__ __forceinline__ uint32_t smem_u32(const void* p) {
    return (uint32_t)__cvta_generic_to_shared(p);
}

#define CP16(dst, src)                                                        \
    asm volatile("cp.async.cg.shared.global [%0], [%1], 16;"                  \
                 :: "r"(dst), "l"(src) : "memory")
#define CP_COMMIT() asm volatile("cp.async.commit_group;" ::: "memory")
#define CP_WAIT(n)  asm volatile("cp.async.wait_group %0;" :: "n"(n) : "memory")

#define LDSM4(r0, r1, r2, r3, a)                                              \
    asm volatile("ldmatrix.sync.aligned.m8n8.x4.shared.b16 {%0,%1,%2,%3}, [%4];" \
                 : "=r"(r0), "=r"(r1), "=r"(r2), "=r"(r3) : "r"(a))
#define LDSM4T(r0, r1, r2, r3, a)                                             \
    asm volatile("ldmatrix.sync.aligned.m8n8.x4.trans.shared.b16 {%0,%1,%2,%3}, [%4];" \
                 : "=r"(r0), "=r"(r1), "=r"(r2), "=r"(r3) : "r"(a))

#define MMA_BF16(c, a, b0, b1)                                                \
    asm volatile(                                                             \
        "mma.sync.aligned.m16n8k16.row.col.f32.bf16.bf16.f32 "                \
        "{%0,%1,%2,%3},{%4,%5,%6,%7},{%8,%9},{%0,%1,%2,%3};"                  \
        : "+f"((c)[0]), "+f"((c)[1]), "+f"((c)[2]), "+f"((c)[3])              \
        : "r"((a)[0]), "r"((a)[1]), "r"((a)[2]), "r"((a)[3]),                 \
          "r"(b0), "r"(b1))

__device__ __forceinline__ uint32_t swz(int row, int chunk) {
    return (uint32_t)(row * 128 + (((chunk) ^ (row & 7)) << 4));
}
__device__ __forceinline__ void split_pack(float a, float b,
                                           uint32_t& hi, uint32_t& lo) {
    __nv_bfloat16 ha = __float2bfloat16_rn(a);
    __nv_bfloat16 hb = __float2bfloat16_rn(b);
    __nv_bfloat16 la = __float2bfloat16_rn(a - __bfloat162float(ha));
    __nv_bfloat16 lb = __float2bfloat16_rn(b - __bfloat162float(hb));
    hi = ((uint32_t)__bfloat16_as_ushort(hb) << 16) | __bfloat16_as_ushort(ha);
    lo = ((uint32_t)__bfloat16_as_ushort(lb) << 16) | __bfloat16_as_ushort(la);
}
__device__ __forceinline__ void store_pair(__nv_bfloat16* Hp, __nv_bfloat16* Lp,
                                           size_t idx, float v0, float v1) {
    __nv_bfloat16 h0 = __float2bfloat16_rn(v0);
    __nv_bfloat16 h1 = __float2bfloat16_rn(v1);
    ushort2 uh = make_ushort2(__bfloat16_as_ushort(h0), __bfloat16_as_ushort(h1));
    *(ushort2*)&Hp[idx] = uh;
    __nv_bfloat16 l0 = __float2bfloat16_rn(v0 - __bfloat162float(h0));
    __nv_bfloat16 l1 = __float2bfloat16_rn(v1 - __bfloat162float(h1));
    ushort2 ul = make_ushort2(__bfloat16_as_ushort(l0), __bfloat16_as_ushort(l1));
    *(ushort2*)&Lp[idx] = ul;
}

// ---------------------------------------------------------------------------
// Convert fp32 -> hi/lo bf16 planes (row-major).
// ---------------------------------------------------------------------------
__global__ __launch_bounds__(256)
void convert_split(const float* __restrict__ X, __nv_bfloat16* __restrict__ Hi,
                   __nv_bfloat16* __restrict__ Lo, int total_pairs)
{
    int e = blockIdx.x * 256 + threadIdx.x;
    if (e >= total_pairs) return;
    float2 v = *(const float2*)(X + (size_t)e * 2);
    __nv_bfloat16 h0 = __float2bfloat16_rn(v.x);
    __nv_bfloat16 l0 = __float2bfloat16_rn(v.x - __bfloat162float(h0));
    __nv_bfloat16 h1 = __float2bfloat16_rn(v.y);
    __nv_bfloat16 l1 = __float2bfloat16_rn(v.y - __bfloat162float(h1));
    uint32_t hp = ((uint32_t)__bfloat16_as_ushort(h1) << 16) | __bfloat16_as_ushort(h0);
    uint32_t lp = ((uint32_t)__bfloat16_as_ushort(l1) << 16) | __bfloat16_as_ushort(l0);
    *(uint32_t*)((char*)Hi + (size_t)e * 4) = hp;
    *(uint32_t*)((char*)Lo + (size_t)e * 4) = lp;
}

// ---------------------------------------------------------------------------
// bf16 split-2 tensor GEMM, CTA tile 128x256, BK=64, warp tile 64x64.
// 256 threads = 8 warps (2M x 4N). Stage 96KB x2.
// QKV=true: scatter q/k/v hi/lo planes (q pre-scaled).
// ---------------------------------------------------------------------------
#define GSTAGE 98304
#define GEMM_SMEM (2*GSTAGE)   // 192 KB

template<bool QKV, bool HAS_BIAS>
__global__ __launch_bounds__(256)
void gemm_bf16(const __nv_bfloat16* __restrict__ Ah,
               const __nv_bfloat16* __restrict__ Al,
               const __nv_bfloat16* __restrict__ Bh,
               const __nv_bfloat16* __restrict__ Bl,
               const float* __restrict__ bias, float* __restrict__ Out,
               __nv_bfloat16* Qh, __nv_bfloat16* Ql,
               __nv_bfloat16* Kh, __nv_bfloat16* Kl,
               __nv_bfloat16* Vh, __nv_bfloat16* Vl,
               int M, int N, int K)
{
    extern __shared__ __align__(128) char sm[];
    const int tid  = threadIdx.x;
    const int warp = tid >> 5;
    const int lane = tid & 31;
    const int wm   = warp & 1;        // 2 warps along M (64 rows)
    const int wn   = warp >> 1;       // 4 warps along N (64 cols)
    const int grp  = lane >> 3;
    const int j    = lane & 7;
    const int bm   = blockIdx.y * 128;
    const int bn   = blockIdx.x * 256;

    float c[4][8][4];
    #pragma unroll
    for (int a = 0; a < 4; a++)
        #pragma unroll
        for (int b = 0; b < 8; b++)
            #pragma unroll
            for (int q = 0; q < 4; q++) c[a][b][q] = 0.f;

    const uint32_t smem0 = smem_u32(sm);
    const int NKC = K >> 6;

    // copy helper: stage layout [Ah 16K | Al 16K | Bh 32K | Bl 32K]
    auto load_stage = [&](uint32_t sbase, int k0) {
        #pragma unroll
        for (int i = 0; i < 8; i++) {            // A planes: 2048 chunks
            int ci = i * 256 + tid;
            int pl = i >> 2;                     // 0..3 -> Ah, 4..7 -> Al
            int r  = (ci & 1023) >> 3, cc = ci & 7;
            const __nv_bfloat16* src = (pl ? Al : Ah)
                + (size_t)(bm + r) * K + k0 + cc * 8;
            CP16(sbase + pl * 16384 + swz(r, cc), src);
        }
        #pragma unroll
        for (int i2 = 0; i2 < 16; i2++) {        // B planes: 4096 chunks
            int ci = i2 * 256 + tid;
            int pl = i2 >> 3;                    // 0..7 -> Bh, 8..15 -> Bl
            int r  = (ci & 2047) >> 3, cc = ci & 7;
            const __nv_bfloat16* src = (pl ? Bl : Bh)
                + (size_t)(bn + r) * K + k0 + cc * 8;
            CP16(sbase + 32768 + pl * 32768 + swz(r, cc), src);
        }
        CP_COMMIT();
    };

    load_stage(smem0, 0);

    for (int t = 0; t < NKC; t++) {
        if (t + 1 < NKC) {
            load_stage(smem0 + ((t + 1) & 1) * GSTAGE, (t + 1) << 6);
            CP_WAIT(1);
        } else {
            CP_WAIT(0);
        }
        __syncthreads();

        uint32_t base = smem0 + (t & 1) * GSTAGE;
        uint32_t sAh = base, sAl = base + 16384;
        uint32_t sBh = base + 32768, sBl = base + 65536;

        #pragma unroll
        for (int ks = 0; ks < 4; ks++) {
            int kch = ks << 1;
            uint32_t ah[4][4], al[4][4];
            #pragma unroll
            for (int mt = 0; mt < 4; mt++) {
                int row = wm * 64 + mt * 16 + ((grp & 1) << 3) + j;
                uint32_t off = swz(row, kch + (grp >> 1));
                LDSM4(ah[mt][0], ah[mt][1], ah[mt][2], ah[mt][3], sAh + off);
                LDSM4(al[mt][0], al[mt][1], al[mt][2], al[mt][3], sAl + off);
            }
            #pragma unroll
            for (int nb = 0; nb < 4; nb++) {
                int rowb = wn * 64 + nb * 16 + ((grp >> 1) << 3) + j;
                uint32_t offb = swz(rowb, kch + (grp & 1));
                uint32_t bh[4], bl[4];
                LDSM4(bh[0], bh[1], bh[2], bh[3], sBh + offb);
                LDSM4(bl[0], bl[1], bl[2], bl[3], sBl + offb);
                #pragma unroll
                for (int mt = 0; mt < 4; mt++) {
                    MMA_BF16(c[mt][nb*2],   ah[mt], bh[0], bh[1]);
                    MMA_BF16(c[mt][nb*2],   ah[mt], bl[0], bl[1]);
                    MMA_BF16(c[mt][nb*2],   al[mt], bh[0], bh[1]);
                    MMA_BF16(c[mt][nb*2+1], ah[mt], bh[2], bh[3]);
                    MMA_BF16(c[mt][nb*2+1], ah[mt], bl[2], bl[3]);
                    MMA_BF16(c[mt][nb*2+1], al[mt], bh[2], bh[3]);
                }
            }
        }
        __syncthreads();
    }

    #pragma unroll
    for (int mt = 0; mt < 4; mt++) {
        int r0 = bm + wm * 64 + mt * 16 + (lane >> 2);
        #pragma unroll
        for (int ng = 0; ng < 8; ng++) {
            int col = bn + wn * 64 + ng * 8 + (lane & 3) * 2;
            if (!QKV) {
                float2 v0 = make_float2(c[mt][ng][0], c[mt][ng][1]);
                float2 v1 = make_float2(c[mt][ng][2], c[mt][ng][3]);
                if (HAS_BIAS) {
                    float2 bv = *(const float2*)&bias[col];
                    v0.x += bv.x; v0.y += bv.y;
                    v1.x += bv.x; v1.y += bv.y;
                }
                *(float2*)&Out[(size_t)r0 * N + col] = v0;
                *(float2*)&Out[(size_t)(r0 + 8) * N + col] = v1;
            } else {
                int h  = col / 192;
                int wc = col - h * 192;
                int ty = wc >> 6;
                int d  = wc & 63;
                __nv_bfloat16* Hp = (ty == 0) ? Qh : (ty == 1) ? Kh : Vh;
                __nv_bfloat16* Lp = (ty == 0) ? Ql : (ty == 1) ? Kl : Vl;
                float sc = (ty == 0) ? 0.125f : 1.0f;
                #pragma unroll
                for (int half = 0; half < 2; half++) {
                    int tg2 = r0 + half * 8;
                    size_t idx = (((size_t)((tg2 >> 11) * Hh + h)) * Tt
                                  + (tg2 & 2047)) * HDd + d;
                    store_pair(Hp, Lp, idx,
                               c[mt][ng][half*2] * sc, c[mt][ng][half*2+1] * sc);
                }
            }
        }
    }
}

// ---------------------------------------------------------------------------
// Tensor-core causal flash attention. Bq=128 (8 warps x m16), Bk=64.
// Split-2 bf16 for QK^T and PV. Writes O as hi/lo bf16 planes (proj A input).
// smem: Q 32KB + 2 KV stages (32KB each) = 96KB -> 2 CTAs/SM.
// ---------------------------------------------------------------------------
#define FA_SMEM (32768 + 2*32768)

__global__ __launch_bounds__(256)
void flash_attn_tc(const __nv_bfloat16* __restrict__ qh, const __nv_bfloat16* __restrict__ ql,
                   const __nv_bfloat16* __restrict__ kh, const __nv_bfloat16* __restrict__ kl,
                   const __nv_bfloat16* __restrict__ vh, const __nv_bfloat16* __restrict__ vl,
                   __nv_bfloat16* __restrict__ Oh, __nv_bfloat16* __restrict__ Ol)
{
    extern __shared__ __align__(128) char sm[];
    const uint32_t s0  = smem_u32(sm);
    const uint32_t sQh = s0, sQl = s0 + 16384;

    const int bh = blockIdx.x;
    const int qt = (gridDim.y - 1) - blockIdx.y;   // heavy tiles first
    const int tid = threadIdx.x, w = tid >> 5, lane = tid & 31;
    const int g = lane >> 2, tg = lane & 3;
    const int grp = lane >> 3, j = lane & 7;

    const size_t pb = (size_t)bh * Tt * HDd;
    const int nkt = 2 * qt + 2;

    // ---- load Q tile (128x64, hi+lo): 2048 chunks / 256 threads
    #pragma unroll
    for (int i = 0; i < 8; i++) {
        int ci = i * 256 + tid;
        int pl = i >> 2;
        int r = (ci & 1023) >> 3, cc = ci & 7;
        const __nv_bfloat16* src = (pl ? ql : qh)
            + pb + (size_t)(qt * 128 + r) * HDd + cc * 8;
        CP16((pl ? sQl : sQh) + swz(r, cc), src);
    }
    CP_COMMIT();

    // ---- prefetch KV tile 0: 2048 chunks (4 planes x 512)
    {
        uint32_t dst0 = s0 + 32768;
        #pragma unroll
        for (int i = 0; i < 8; i++) {
            int ci = i * 256 + tid;
            int pl = i >> 1;                 // 0:kh 1:kl 2:vh 3:vl
            int r = (ci & 511) >> 3, cc = ci & 7;
            const __nv_bfloat16* src =
                ((pl == 0) ? kh : (pl == 1) ? kl : (pl == 2) ? vh : vl)
                + pb + (size_t)r * HDd + cc * 8;
            CP16(dst0 + pl * 8192 + swz(r, cc), src);
        }
        CP_COMMIT();
    }
    CP_WAIT(1);            // Q done
    __syncthreads();

    // ---- Q fragments register-resident
    uint32_t qhf[4][4], qlf[4][4];
    #pragma unroll
    for (int kb = 0; kb < 4; kb++) {
        int row = w * 16 + ((grp & 1) << 3) + j;
        uint32_t off = swz(row, kb * 2 + (grp >> 1));
        LDSM4(qhf[kb][0], qhf[kb][1], qhf[kb][2], qhf[kb][3], sQh + off);
        LDSM4(qlf[kb][0], qlf[kb][1], qlf[kb][2], qlf[kb][3], sQl + off);
    }

    float o[8][4];
    #pragma unroll
    for (int nb = 0; nb < 8; nb++)
        #pragma unroll
        for (int e = 0; e < 4; e++) o[nb][e] = 0.f;
    float mA = -INFINITY, mB = -INFINITY, lA = 0.f, lB = 0.f;

    const int wrow0 = qt * 128 + w * 16;   // warp's first global query row

    for (int kt = 0; kt < nkt; kt++) {
        if (kt + 1 < nkt) {
            uint32_t dst = s0 + 32768 + ((kt + 1) & 1) * 32768;
            #pragma unroll
            for (int i = 0; i < 8; i++) {
                int ci = i * 256 + tid;
                int pl = i >> 1;
                int r = (ci & 511) >> 3, cc = ci & 7;
                const __nv_bfloat16* src =
                    ((pl == 0) ? kh : (pl == 1) ? kl : (pl == 2) ? vh : vl)
                    + pb + (size_t)((kt + 1) * 64 + r) * HDd + cc * 8;
                CP16(dst + pl * 8192 + swz(r, cc), src);
            }
            CP_COMMIT();
            CP_WAIT(1);
        } else {
            CP_WAIT(0);
        }
        __syncthreads();

        // warps whose rows are entirely above this key tile skip all work
        if (kt * 64 <= wrow0 + 15) {
            uint32_t kbse = s0 + 32768 + (kt & 1) * 32768;
            uint32_t sKh = kbse, sKl = kbse + 8192;
            uint32_t sVh = kbse + 16384, sVl = kbse + 24576;

            // ---- S = Q K^T (split-2: 3 products)
            float s[8][4];
            #pragma unroll
            for (int nb = 0; nb < 8; nb++)
                #pragma unroll
                for (int e = 0; e < 4; e++) s[nb][e] = 0.f;

            #pragma unroll
            for (int kb = 0; kb < 4; kb++) {
                #pragma unroll
                for (int p = 0; p < 4; p++) {
                    int rowb = p * 16 + ((grp >> 1) << 3) + j;
                    uint32_t off = swz(rowb, kb * 2 + (grp & 1));
                    uint32_t bhr[4], blr[4];
                    LDSM4(bhr[0], bhr[1], bhr[2], bhr[3], sKh + off);
                    LDSM4(blr[0], blr[1], blr[2], blr[3], sKl + off);
                    MMA_BF16(s[p*2],   qhf[kb], bhr[0], bhr[1]);
                    MMA_BF16(s[p*2],   qhf[kb], blr[0], blr[1]);
                    MMA_BF16(s[p*2],   qlf[kb], bhr[0], bhr[1]);
                    MMA_BF16(s[p*2+1], qhf[kb], bhr[2], bhr[3]);
                    MMA_BF16(s[p*2+1], qhf[kb], blr[2], blr[3]);
                    MMA_BF16(s[p*2+1], qlf[kb], bhr[2], bhr[3]);
                }
            }

            // ---- causal mask (diagonal zone only)
            if (kt * 64 + 63 > wrow0) {
                int rowA = wrow0 + g, rowB = rowA + 8;
                #pragma unroll
                for (int nb = 0; nb < 8; nb++) {
                    int c0 = kt * 64 + nb * 8 + tg * 2;
                    if (c0 > rowA)     s[nb][0] = -INFINITY;
                    if (c0 + 1 > rowA) s[nb][1] = -INFINITY;
                    if (c0 > rowB)     s[nb][2] = -INFINITY;
                    if (c0 + 1 > rowB) s[nb][3] = -INFINITY;
                }
            }

            // ---- online softmax
            float mxA = -INFINITY, mxB = -INFINITY;
            #pragma unroll
            for (int nb = 0; nb < 8; nb++) {
                mxA = fmaxf(mxA, fmaxf(s[nb][0], s[nb][1]));
                mxB = fmaxf(mxB, fmaxf(s[nb][2], s[nb][3]));
            }
            #pragma unroll
            for (int d = 1; d < 4; d <<= 1) {
                mxA = fmaxf(mxA, __shfl_xor_sync(0xffffffffu, mxA, d));
                mxB = fmaxf(mxB, __shfl_xor_sync(0xffffffffu, mxB, d));
            }
            float mAn = fmaxf(mA, mxA), mBn = fmaxf(mB, mxB);
            float aA = __expf(mA - mAn), aB = __expf(mB - mBn);
            float sumA = 0.f, sumB = 0.f;
            #pragma unroll
            for (int nb = 0; nb < 8; nb++) {
                s[nb][0] = __expf(s[nb][0] - mAn); sumA += s[nb][0];
                s[nb][1] = __expf(s[nb][1] - mAn); sumA += s[nb][1];
                s[nb][2] = __expf(s[nb][2] - mBn); sumB += s[nb][2];
                s[nb][3] = __expf(s[nb][3] - mBn); sumB += s[nb][3];
            }
            #pragma unroll
            for (int d = 1; d < 4; d <<= 1) {
                sumA += __shfl_xor_sync(0xffffffffu, sumA, d);
                sumB += __shfl_xor_sync(0xffffffffu, sumB, d);
            }
            lA = lA * aA + sumA; lB = lB * aB + sumB;
            mA = mAn; mB = mBn;
            #pragma unroll
            for (int nb = 0; nb < 8; nb++) {
                o[nb][0] *= aA; o[nb][1] *= aA;
                o[nb][2] *= aB; o[nb][3] *= aB;
            }

            // ---- O += P V (split-2: 3 products), V via ldmatrix.trans
            #pragma unroll
            for (int kb = 0; kb < 4; kb++) {
                uint32_t ph[4], pl[4];
                split_pack(s[2*kb][0],   s[2*kb][1],   ph[0], pl[0]);
                split_pack(s[2*kb][2],   s[2*kb][3],   ph[1], pl[1]);
                split_pack(s[2*kb+1][0], s[2*kb+1][1], ph[2], pl[2]);
                split_pack(s[2*kb+1][2], s[2*kb+1][3], ph[3], pl[3]);
                #pragma unroll
                for (int p = 0; p < 4; p++) {
                    int keyrow = kb * 16 + ((grp & 1) << 3) + j;
                    uint32_t off = swz(keyrow, p * 2 + (grp >> 1));
                    uint32_t vhr[4], vlr[4];
                    LDSM4T(vhr[0], vhr[1], vhr[2], vhr[3], sVh + off);
                    LDSM4T(vlr[0], vlr[1], vlr[2], vlr[3], sVl + off);
                    MMA_BF16(o[p*2],   ph, vhr[0], vhr[1]);
                    MMA_BF16(o[p*2],   ph, vlr[0], vlr[1]);
                    MMA_BF16(o[p*2],   pl, vhr[0], vhr[1]);
                    MMA_BF16(o[p*2+1], ph, vhr[2], vhr[3]);
                    MMA_BF16(o[p*2+1], ph, vlr[2], vlr[3]);
                    MMA_BF16(o[p*2+1], pl, vhr[2], vhr[3]);
                }
            }
        }
        __syncthreads();
    }

    // ---- normalize + store O hi/lo into proj A planes [t][C]
    float invA = 1.f / lA, invB = 1.f / lB;
    int b = bh >> 4, h = bh & 15;
    int tA = b * Tt + qt * 128 + w * 16 + g;
    #pragma unroll
    for (int nb = 0; nb < 8; nb++) {
        int col = h * 64 + nb * 8 + tg * 2;
        store_pair(Oh, Ol, (size_t)tA * Cc + col, o[nb][0]*invA, o[nb][1]*invA);
        store_pair(Oh, Ol, (size_t)(tA + 8) * Cc + col, o[nb][2]*invB, o[nb][3]*invB);
    }
}

// ---------------------------------------------------------------------------
extern "C" void kernel_launch(void* const* d_in, const int* in_sizes, int n_in,
                              void* d_out, int out_size)
{
    const float* x     = (const float*)d_in[0];
    const float* Wqkv  = (const float*)d_in[1];
    const float* Wproj = (const float*)d_in[2];
    const float* bproj = (const float*)d_in[3];
    float* out = (float*)d_out;

    __nv_bfloat16 *ah, *al, *bh, *bl, *qh, *ql, *kh, *kl, *vh, *vl;
    cudaGetSymbolAddress((void**)&ah, g_ah);
    cudaGetSymbolAddress((void**)&al, g_al);
    cudaGetSymbolAddress((void**)&bh, g_bh);
    cudaGetSymbolAddress((void**)&bl, g_bl);
    cudaGetSymbolAddress((void**)&qh, g_qh);
    cudaGetSymbolAddress((void**)&ql, g_ql);
    cudaGetSymbolAddress((void**)&kh, g_kh);
    cudaGetSymbolAddress((void**)&kl, g_kl);
    cudaGetSymbolAddress((void**)&vh, g_vh);
    cudaGetSymbolAddress((void**)&vl, g_vl);

    cudaFuncSetAttribute((const void*)gemm_bf16<true, false>,
                         cudaFuncAttributeMaxDynamicSharedMemorySize, GEMM_SMEM);
    cudaFuncSetAttribute((const void*)gemm_bf16<false, true>,
                         cudaFuncAttributeMaxDynamicSharedMemorySize, GEMM_SMEM);
    cudaFuncSetAttribute((const void*)flash_attn_tc,
                         cudaFuncAttributeMaxDynamicSharedMemorySize, FA_SMEM);

    // 1) split-convert x and Wqkv
    convert_split<<<(MROWS * Cc / 2 + 255) / 256, 256>>>(x, ah, al, MROWS * Cc / 2);
    convert_split<<<(THREEC * Cc / 2 + 255) / 256, 256>>>(Wqkv, bh, bl, THREEC * Cc / 2);

    // 2) QKV projection -> q/k/v hi/lo planes (q pre-scaled)
    gemm_bf16<true, false><<<dim3(THREEC / 256, MROWS / 128), 256, GEMM_SMEM>>>(
        ah, al, bh, bl, nullptr, nullptr, qh, ql, kh, kl, vh, vl,
        MROWS, THREEC, Cc);

    // 3) Tensor-core causal flash attention -> proj A planes
    flash_attn_tc<<<dim3(BH, Tt / 128), 256, FA_SMEM>>>(
        qh, ql, kh, kl, vh, vl, ah, al);

    // 4) split-convert Wproj
    convert_split<<<(Cc * Cc / 2 + 255) / 256, 256>>>(Wproj, bh, bl, Cc * Cc / 2);

    // 5) Output projection (+bias)
    gemm_bf16<false, true><<<dim3(Cc / 256, MROWS / 128), 256, GEMM_SMEM>>>(
        ah, al, bh, bl, bproj, out, nullptr, nullptr, nullptr, nullptr,
        nullptr, nullptr, MROWS, Cc, Cc);
}

// round 7
// speedup vs baseline: 4.8265x; 1.1865x over previous
#include <cuda_runtime.h>
#include <cuda_bf16.h>
#include <math.h>
#include <stdint.h>

// Problem constants
#define Bb    4
#define Tt    2048
#define Cc    1024
#define Hh    16
#define HDd   64
#define MROWS (Bb*Tt)      // 8192
#define THREEC (3*Cc)      // 3072
#define BH    (Bb*Hh)      // 64

// Scratch: block-formatted operands (allocation-free rule: __device__ globals)
// A/B blocks: 16KB = 128 rows x 128B; chunks 0-3 = hi plane k0..31, 4-7 = lo.
__device__ __nv_bfloat16 g_Ablk[(size_t)MROWS * Cc * 2];    // 32MB (A for both GEMMs)
__device__ __nv_bfloat16 g_Bblk[(size_t)THREEC * Cc * 2];   // 12MB (B for both GEMMs)
// FA operands: plane-pure swizzled blocks. Q: 16KB (128x64); K/V: 8KB (64x64).
__device__ __nv_bfloat16 g_qh[(size_t)BH * Tt * HDd];
__device__ __nv_bfloat16 g_ql[(size_t)BH * Tt * HDd];
__device__ __nv_bfloat16 g_kh[(size_t)BH * Tt * HDd];
__device__ __nv_bfloat16 g_kl[(size_t)BH * Tt * HDd];
__device__ __nv_bfloat16 g_vh[(size_t)BH * Tt * HDd];
__device__ __nv_bfloat16 g_vl[(size_t)BH * Tt * HDd];

__device__ __forceinline__ uint32_t smem_u32(const void* p) {
    return (uint32_t)__cvta_generic_to_shared(p);
}
__device__ __forceinline__ void mbar_init(uint32_t a, uint32_t cnt) {
    asm volatile("mbarrier.init.shared.b64 [%0], %1;" :: "r"(a), "r"(cnt) : "memory");
}
__device__ __forceinline__ void mbar_expect(uint32_t a, uint32_t tx) {
    asm volatile("mbarrier.arrive.expect_tx.shared.b64 _, [%0], %1;"
                 :: "r"(a), "r"(tx) : "memory");
}
__device__ __forceinline__ void mbar_wait(uint32_t a, uint32_t ph) {
    asm volatile(
        "{\n\t.reg .pred P;\n\t"
        "WL%=:\n\t"
        "mbarrier.try_wait.parity.shared::cta.b64 P, [%0], %1, 0x989680;\n\t"
        "@!P bra WL%=;\n\t}"
        :: "r"(a), "r"(ph) : "memory");
}
__device__ __forceinline__ void bulk_g2s(uint32_t dst, const void* src,
                                         uint32_t bytes, uint32_t mbar) {
    asm volatile(
        "cp.async.bulk.shared::cluster.global.mbarrier::complete_tx::bytes "
        "[%0], [%1], %2, [%3];"
        :: "r"(dst), "l"(src), "r"(bytes), "r"(mbar) : "memory");
}

#define LDSM4(r0, r1, r2, r3, a)                                              \
    asm volatile("ldmatrix.sync.aligned.m8n8.x4.shared.b16 {%0,%1,%2,%3}, [%4];" \
                 : "=r"(r0), "=r"(r1), "=r"(r2), "=r"(r3) : "r"(a))
#define LDSM4T(r0, r1, r2, r3, a)                                             \
    asm volatile("ldmatrix.sync.aligned.m8n8.x4.trans.shared.b16 {%0,%1,%2,%3}, [%4];" \
                 : "=r"(r0), "=r"(r1), "=r"(r2), "=r"(r3) : "r"(a))
#define MMA_BF16(c, a, b0, b1)                                                \
    asm volatile(                                                             \
        "mma.sync.aligned.m16n8k16.row.col.f32.bf16.bf16.f32 "                \
        "{%0,%1,%2,%3},{%4,%5,%6,%7},{%8,%9},{%0,%1,%2,%3};"                  \
        : "+f"((c)[0]), "+f"((c)[1]), "+f"((c)[2]), "+f"((c)[3])              \
        : "r"((a)[0]), "r"((a)[1]), "r"((a)[2]), "r"((a)[3]),                 \
          "r"(b0), "r"(b1))

__device__ __forceinline__ uint32_t swz(int row, int chunk) {
    return (uint32_t)(row * 128 + (((chunk) ^ (row & 7)) << 4));
}
__device__ __forceinline__ void split2(float a, float b, uint32_t& hi, uint32_t& lo) {
    __nv_bfloat16 ha = __float2bfloat16_rn(a);
    __nv_bfloat16 hb = __float2bfloat16_rn(b);
    __nv_bfloat16 la = __float2bfloat16_rn(a - __bfloat162float(ha));
    __nv_bfloat16 lb = __float2bfloat16_rn(b - __bfloat162float(hb));
    hi = ((uint32_t)__bfloat16_as_ushort(hb) << 16) | __bfloat16_as_ushort(ha);
    lo = ((uint32_t)__bfloat16_as_ushort(lb) << 16) | __bfloat16_as_ushort(la);
}

// ---------------------------------------------------------------------------
// Convert fp32 [R,1024] row-major -> interleaved hi/lo swizzled 16KB blocks.
// ---------------------------------------------------------------------------
__global__ __launch_bounds__(256)
void convert_blk(const float* __restrict__ X, __nv_bfloat16* __restrict__ Dst,
                 int total_pairs)
{
    int e = blockIdx.x * 256 + threadIdx.x;
    if (e >= total_pairs) return;
    int r = e >> 9;              // row (K=1024 -> 512 pairs/row)
    int k = (e & 511) * 2;
    float2 v = *(const float2*)(X + (size_t)r * 1024 + k);
    uint32_t hp, lp;
    split2(v.x, v.y, hp, lp);
    int mt = r >> 7, rr = r & 127, kt = k >> 5, kc = k & 31;
    char* d = (char*)Dst + ((size_t)(mt * 32 + kt)) * 16384;
    *(uint32_t*)(d + swz(rr, kc >> 3) + (kc & 7) * 2)       = hp;
    *(uint32_t*)(d + swz(rr, (kc >> 3) + 4) + (kc & 7) * 2) = lp;
}

// ---------------------------------------------------------------------------
// bf16 split-2 tensor GEMM on pre-swizzled blocks. 128x128, BK=32, 2 stages,
// bulk loads, 256 thr (4M x 2N warps, warp 32x64), 2 CTAs/SM.
// QKV=true: scatter q/k/v plane blocks (q pre-scaled).
// ---------------------------------------------------------------------------
#define GST 32768
#define GEMM_SMEM (1024 + 2*GST)

template<bool QKV, bool HAS_BIAS>
__global__ __launch_bounds__(256, 2)
void gemm_blk(const __nv_bfloat16* __restrict__ Ablk,
              const __nv_bfloat16* __restrict__ Bblk,
              const float* __restrict__ bias, float* __restrict__ Out,
              __nv_bfloat16* Qh, __nv_bfloat16* Ql,
              __nv_bfloat16* Kh, __nv_bfloat16* Kl,
              __nv_bfloat16* Vh, __nv_bfloat16* Vl, int N)
{
    extern __shared__ __align__(1024) char sm[];
    const uint32_t s0 = smem_u32(sm);
    const uint32_t FB0 = s0, FB1 = s0 + 8;
    const uint32_t buf0 = s0 + 1024;
    const int tid = threadIdx.x, warp = tid >> 5, lane = tid & 31;
    const int wm = warp & 3, wn = warp >> 2;
    const int grp = lane >> 3, j = lane & 7;
    const int bm = blockIdx.y, bn = blockIdx.x;   // 128-tiles
    const int NKC = 32;

    if (tid == 0) { mbar_init(FB0, 1); mbar_init(FB1, 1); }
    __syncthreads();
    if (tid == 0) {
        #pragma unroll
        for (int p = 0; p < 2; p++) {
            uint32_t fb = p ? FB1 : FB0;
            mbar_expect(fb, 2 * 16384);
            bulk_g2s(buf0 + p * GST,
                     (const char*)Ablk + ((size_t)bm * NKC + p) * 16384, 16384, fb);
            bulk_g2s(buf0 + p * GST + 16384,
                     (const char*)Bblk + ((size_t)bn * NKC + p) * 16384, 16384, fb);
        }
    }

    float c[2][8][4];
    #pragma unroll
    for (int a = 0; a < 2; a++)
        #pragma unroll
        for (int b = 0; b < 8; b++)
            #pragma unroll
            for (int q = 0; q < 4; q++) c[a][b][q] = 0.f;

    for (int t = 0; t < NKC; t++) {
        mbar_wait((t & 1) ? FB1 : FB0, (t >> 1) & 1);
        uint32_t sA = buf0 + (t & 1) * GST;
        uint32_t sB = sA + 16384;

        #pragma unroll
        for (int ks = 0; ks < 2; ks++) {
            uint32_t ah[2][4], al[2][4];
            #pragma unroll
            for (int mt = 0; mt < 2; mt++) {
                int row = wm * 32 + mt * 16 + ((grp & 1) << 3) + j;
                int ch = ks * 2 + (grp >> 1);
                LDSM4(ah[mt][0], ah[mt][1], ah[mt][2], ah[mt][3], sA + swz(row, ch));
                LDSM4(al[mt][0], al[mt][1], al[mt][2], al[mt][3], sA + swz(row, ch + 4));
            }
            #pragma unroll
            for (int nb = 0; nb < 4; nb++) {
                int rowb = wn * 64 + nb * 16 + ((grp >> 1) << 3) + j;
                int chb = ks * 2 + (grp & 1);
                uint32_t bh[4], bl[4];
                LDSM4(bh[0], bh[1], bh[2], bh[3], sB + swz(rowb, chb));
                LDSM4(bl[0], bl[1], bl[2], bl[3], sB + swz(rowb, chb + 4));
                #pragma unroll
                for (int mt = 0; mt < 2; mt++) {
                    MMA_BF16(c[mt][nb*2],   ah[mt], bh[0], bh[1]);
                    MMA_BF16(c[mt][nb*2],   ah[mt], bl[0], bl[1]);
                    MMA_BF16(c[mt][nb*2],   al[mt], bh[0], bh[1]);
                    MMA_BF16(c[mt][nb*2+1], ah[mt], bh[2], bh[3]);
                    MMA_BF16(c[mt][nb*2+1], ah[mt], bl[2], bl[3]);
                    MMA_BF16(c[mt][nb*2+1], al[mt], bh[2], bh[3]);
                }
            }
        }
        __syncthreads();
        if (tid == 0 && t + 2 < NKC) {
            uint32_t fb = (t & 1) ? FB1 : FB0;
            mbar_expect(fb, 2 * 16384);
            bulk_g2s(sA, (const char*)Ablk + ((size_t)bm * NKC + t + 2) * 16384,
                     16384, fb);
            bulk_g2s(sB, (const char*)Bblk + ((size_t)bn * NKC + t + 2) * 16384,
                     16384, fb);
        }
    }

    // epilogue
    #pragma unroll
    for (int mt = 0; mt < 2; mt++) {
        int r0 = bm * 128 + wm * 32 + mt * 16 + (lane >> 2);
        #pragma unroll
        for (int ng = 0; ng < 8; ng++) {
            int col = bn * 128 + wn * 64 + ng * 8 + (lane & 3) * 2;
            if (!QKV) {
                float2 v0 = make_float2(c[mt][ng][0], c[mt][ng][1]);
                float2 v1 = make_float2(c[mt][ng][2], c[mt][ng][3]);
                if (HAS_BIAS) {
                    float2 bv = *(const float2*)&bias[col];
                    v0.x += bv.x; v0.y += bv.y;
                    v1.x += bv.x; v1.y += bv.y;
                }
                *(float2*)&Out[(size_t)r0 * N + col] = v0;
                *(float2*)&Out[(size_t)(r0 + 8) * N + col] = v1;
            } else {
                int h  = col / 192;
                int wc = col - h * 192;
                int ty = wc >> 6;
                int d  = wc & 63;
                __nv_bfloat16* Hp = (ty == 0) ? Qh : (ty == 1) ? Kh : Vh;
                __nv_bfloat16* Lp = (ty == 0) ? Ql : (ty == 1) ? Kl : Vl;
                float sc = (ty == 0) ? 0.125f : 1.0f;
                #pragma unroll
                for (int half = 0; half < 2; half++) {
                    int m = r0 + half * 8;
                    int b = m >> 11, tt = m & 2047;
                    int bh2 = b * Hh + h;
                    uint32_t hp, lp;
                    split2(c[mt][ng][half*2] * sc, c[mt][ng][half*2+1] * sc, hp, lp);
                    size_t base; uint32_t off;
                    if (ty == 0) {   // Q: 16KB blocks (128 rows)
                        base = ((size_t)bh2 * 16 + (tt >> 7)) * 16384;
                        off  = swz(tt & 127, d >> 3) + (d & 7) * 2;
                    } else {         // K/V: 8KB blocks (64 rows)
                        base = ((size_t)bh2 * 32 + (tt >> 6)) * 8192;
                        off  = swz(tt & 63, d >> 3) + (d & 7) * 2;
                    }
                    *(uint32_t*)((char*)Hp + base + off) = hp;
                    *(uint32_t*)((char*)Lp + base + off) = lp;
                }
            }
        }
    }
}

// ---------------------------------------------------------------------------
// Tensor-core causal flash attention on pre-swizzled blocks.
// Bq=128 (8 warps x m16), Bk=64, 2 KV stages via bulk, Q from smem per kb.
// smem: hdr 1KB + Q 32KB + 2x32KB = 97KB -> 2 CTAs/SM.
// Writes O as interleaved proj-A blocks.
// ---------------------------------------------------------------------------
#define FA_SMEM (1024 + 32768 + 2*32768)

__global__ __launch_bounds__(256, 2)
void flash_attn_tc(const __nv_bfloat16* __restrict__ qh, const __nv_bfloat16* __restrict__ ql,
                   const __nv_bfloat16* __restrict__ kh, const __nv_bfloat16* __restrict__ kl,
                   const __nv_bfloat16* __restrict__ vh, const __nv_bfloat16* __restrict__ vl,
                   __nv_bfloat16* __restrict__ OA)
{
    extern __shared__ __align__(1024) char sm[];
    const uint32_t s0  = smem_u32(sm);
    const uint32_t QB = s0, FB0 = s0 + 8, FB1 = s0 + 16;
    const uint32_t sQh = s0 + 1024, sQl = sQh + 16384;
    const uint32_t kvb = s0 + 1024 + 32768;

    const int bh = blockIdx.x;
    const int qt = (gridDim.y - 1) - blockIdx.y;
    const int tid = threadIdx.x, w = tid >> 5, lane = tid & 31;
    const int g = lane >> 2, tg = lane & 3;
    const int grp = lane >> 3, j = lane & 7;
    const int nkt = 2 * qt + 2;

    if (tid == 0) { mbar_init(QB, 1); mbar_init(FB0, 1); mbar_init(FB1, 1); }
    __syncthreads();
    if (tid == 0) {
        mbar_expect(QB, 2 * 16384);
        bulk_g2s(sQh, (const char*)qh + ((size_t)bh * 16 + qt) * 16384, 16384, QB);
        bulk_g2s(sQl, (const char*)ql + ((size_t)bh * 16 + qt) * 16384, 16384, QB);
        #pragma unroll
        for (int p = 0; p < 2; p++) {
            uint32_t fb = p ? FB1 : FB0;
            uint32_t dst = kvb + p * 32768;
            size_t kb_ = ((size_t)bh * 32 + p) * 8192;
            mbar_expect(fb, 32768);
            bulk_g2s(dst,         (const char*)kh + kb_, 8192, fb);
            bulk_g2s(dst + 8192,  (const char*)kl + kb_, 8192, fb);
            bulk_g2s(dst + 16384, (const char*)vh + kb_, 8192, fb);
            bulk_g2s(dst + 24576, (const char*)vl + kb_, 8192, fb);
        }
    }
    mbar_wait(QB, 0);

    float o[8][4];
    #pragma unroll
    for (int nb = 0; nb < 8; nb++)
        #pragma unroll
        for (int e = 0; e < 4; e++) o[nb][e] = 0.f;
    float mA = -INFINITY, mB = -INFINITY, lA = 0.f, lB = 0.f;
    const int wrow0 = qt * 128 + w * 16;

    for (int kt = 0; kt < nkt; kt++) {
        mbar_wait((kt & 1) ? FB1 : FB0, (kt >> 1) & 1);
        uint32_t stg = kvb + (kt & 1) * 32768;
        uint32_t sKh = stg, sKl = stg + 8192;
        uint32_t sVh = stg + 16384, sVl = stg + 24576;

        if (kt * 64 <= wrow0 + 15) {
            // ---- S = Q K^T (split-2: 3 products), Q frags from smem per kb
            float s[8][4];
            #pragma unroll
            for (int nb = 0; nb < 8; nb++)
                #pragma unroll
                for (int e = 0; e < 4; e++) s[nb][e] = 0.f;

            #pragma unroll
            for (int kb = 0; kb < 4; kb++) {
                int qrow = w * 16 + ((grp & 1) << 3) + j;
                uint32_t qoff = swz(qrow, kb * 2 + (grp >> 1));
                uint32_t qhf[4], qlf[4];
                LDSM4(qhf[0], qhf[1], qhf[2], qhf[3], sQh + qoff);
                LDSM4(qlf[0], qlf[1], qlf[2], qlf[3], sQl + qoff);
                #pragma unroll
                for (int p = 0; p < 4; p++) {
                    int rowb = p * 16 + ((grp >> 1) << 3) + j;
                    uint32_t off = swz(rowb, kb * 2 + (grp & 1));
                    uint32_t bhr[4], blr[4];
                    LDSM4(bhr[0], bhr[1], bhr[2], bhr[3], sKh + off);
                    LDSM4(blr[0], blr[1], blr[2], blr[3], sKl + off);
                    MMA_BF16(s[p*2],   qhf, bhr[0], bhr[1]);
                    MMA_BF16(s[p*2],   qhf, blr[0], blr[1]);
                    MMA_BF16(s[p*2],   qlf, bhr[0], bhr[1]);
                    MMA_BF16(s[p*2+1], qhf, bhr[2], bhr[3]);
                    MMA_BF16(s[p*2+1], qhf, blr[2], blr[3]);
                    MMA_BF16(s[p*2+1], qlf, bhr[2], bhr[3]);
                }
            }

            // ---- causal mask (diagonal zone only)
            if (kt * 64 + 63 > wrow0) {
                int rowA = wrow0 + g, rowB = rowA + 8;
                #pragma unroll
                for (int nb = 0; nb < 8; nb++) {
                    int c0 = kt * 64 + nb * 8 + tg * 2;
                    if (c0 > rowA)     s[nb][0] = -INFINITY;
                    if (c0 + 1 > rowA) s[nb][1] = -INFINITY;
                    if (c0 > rowB)     s[nb][2] = -INFINITY;
                    if (c0 + 1 > rowB) s[nb][3] = -INFINITY;
                }
            }

            // ---- online softmax
            float mxA = -INFINITY, mxB = -INFINITY;
            #pragma unroll
            for (int nb = 0; nb < 8; nb++) {
                mxA = fmaxf(mxA, fmaxf(s[nb][0], s[nb][1]));
                mxB = fmaxf(mxB, fmaxf(s[nb][2], s[nb][3]));
            }
            #pragma unroll
            for (int d = 1; d < 4; d <<= 1) {
                mxA = fmaxf(mxA, __shfl_xor_sync(0xffffffffu, mxA, d));
                mxB = fmaxf(mxB, __shfl_xor_sync(0xffffffffu, mxB, d));
            }
            float mAn = fmaxf(mA, mxA), mBn = fmaxf(mB, mxB);
            float aA = __expf(mA - mAn), aB = __expf(mB - mBn);
            float sumA = 0.f, sumB = 0.f;
            #pragma unroll
            for (int nb = 0; nb < 8; nb++) {
                s[nb][0] = __expf(s[nb][0] - mAn); sumA += s[nb][0];
                s[nb][1] = __expf(s[nb][1] - mAn); sumA += s[nb][1];
                s[nb][2] = __expf(s[nb][2] - mBn); sumB += s[nb][2];
                s[nb][3] = __expf(s[nb][3] - mBn); sumB += s[nb][3];
            }
            #pragma unroll
            for (int d = 1; d < 4; d <<= 1) {
                sumA += __shfl_xor_sync(0xffffffffu, sumA, d);
                sumB += __shfl_xor_sync(0xffffffffu, sumB, d);
            }
            lA = lA * aA + sumA; lB = lB * aB + sumB;
            mA = mAn; mB = mBn;
            #pragma unroll
            for (int nb = 0; nb < 8; nb++) {
                o[nb][0] *= aA; o[nb][1] *= aA;
                o[nb][2] *= aB; o[nb][3] *= aB;
            }

            // ---- O += P V (split-2: 3 products)
            #pragma unroll
            for (int kb = 0; kb < 4; kb++) {
                uint32_t ph[4], pl[4];
                split2(s[2*kb][0],   s[2*kb][1],   ph[0], pl[0]);
                split2(s[2*kb][2],   s[2*kb][3],   ph[1], pl[1]);
                split2(s[2*kb+1][0], s[2*kb+1][1], ph[2], pl[2]);
                split2(s[2*kb+1][2], s[2*kb+1][3], ph[3], pl[3]);
                #pragma unroll
                for (int p = 0; p < 4; p++) {
                    int keyrow = kb * 16 + ((grp & 1) << 3) + j;
                    uint32_t off = swz(keyrow, p * 2 + (grp >> 1));
                    uint32_t vhr[4], vlr[4];
                    LDSM4T(vhr[0], vhr[1], vhr[2], vhr[3], sVh + off);
                    LDSM4T(vlr[0], vlr[1], vlr[2], vlr[3], sVl + off);
                    MMA_BF16(o[p*2],   ph, vhr[0], vhr[1]);
                    MMA_BF16(o[p*2],   ph, vlr[0], vlr[1]);
                    MMA_BF16(o[p*2],   pl, vhr[0], vhr[1]);
                    MMA_BF16(o[p*2+1], ph, vhr[2], vhr[3]);
                    MMA_BF16(o[p*2+1], ph, vlr[2], vlr[3]);
                    MMA_BF16(o[p*2+1], pl, vhr[2], vhr[3]);
                }
            }
        }
        __syncthreads();
        if (tid == 0 && kt + 2 < nkt) {
            uint32_t fb = (kt & 1) ? FB1 : FB0;
            uint32_t dst = kvb + (kt & 1) * 32768;
            size_t kb_ = ((size_t)bh * 32 + kt + 2) * 8192;
            mbar_expect(fb, 32768);
            bulk_g2s(dst,         (const char*)kh + kb_, 8192, fb);
            bulk_g2s(dst + 8192,  (const char*)kl + kb_, 8192, fb);
            bulk_g2s(dst + 16384, (const char*)vh + kb_, 8192, fb);
            bulk_g2s(dst + 24576, (const char*)vl + kb_, 8192, fb);
        }
    }

    // ---- normalize + store O as interleaved proj-A blocks
    float invA = 1.f / lA, invB = 1.f / lB;
    int b = bh >> 4, h = bh & 15;
    #pragma unroll
    for (int nb = 0; nb < 8; nb++) {
        int col = h * 64 + nb * 8 + tg * 2;
        int ktc = col >> 5, kc = col & 31;
        #pragma unroll
        for (int half = 0; half < 2; half++) {
            int m = b * Tt + qt * 128 + w * 16 + g + half * 8;
            float inv = half ? invB : invA;
            uint32_t hp, lp;
            split2(o[nb][half*2] * inv, o[nb][half*2+1] * inv, hp, lp);
            char* d = (char*)OA + ((size_t)(m >> 7) * 32 + ktc) * 16384;
            *(uint32_t*)(d + swz(m & 127, kc >> 3) + (kc & 7) * 2)       = hp;
            *(uint32_t*)(d + swz(m & 127, (kc >> 3) + 4) + (kc & 7) * 2) = lp;
        }
    }
}

// ---------------------------------------------------------------------------
extern "C" void kernel_launch(void* const* d_in, const int* in_sizes, int n_in,
                              void* d_out, int out_size)
{
    const float* x     = (const float*)d_in[0];
    const float* Wqkv  = (const float*)d_in[1];
    const float* Wproj = (const float*)d_in[2];
    const float* bproj = (const float*)d_in[3];
    float* out = (float*)d_out;

    __nv_bfloat16 *Ab, *Bbk, *qh, *ql, *kh, *kl, *vh, *vl;
    cudaGetSymbolAddress((void**)&Ab, g_Ablk);
    cudaGetSymbolAddress((void**)&Bbk, g_Bblk);
    cudaGetSymbolAddress((void**)&qh, g_qh);
    cudaGetSymbolAddress((void**)&ql, g_ql);
    cudaGetSymbolAddress((void**)&kh, g_kh);
    cudaGetSymbolAddress((void**)&kl, g_kl);
    cudaGetSymbolAddress((void**)&vh, g_vh);
    cudaGetSymbolAddress((void**)&vl, g_vl);

    cudaFuncSetAttribute((const void*)gemm_blk<true, false>,
                         cudaFuncAttributeMaxDynamicSharedMemorySize, GEMM_SMEM);
    cudaFuncSetAttribute((const void*)gemm_blk<false, true>,
                         cudaFuncAttributeMaxDynamicSharedMemorySize, GEMM_SMEM);
    cudaFuncSetAttribute((const void*)flash_attn_tc,
                         cudaFuncAttributeMaxDynamicSharedMemorySize, FA_SMEM);

    // 1) block-convert x and Wqkv
    convert_blk<<<(MROWS * 512 + 255) / 256, 256>>>(x, Ab, MROWS * 512);
    convert_blk<<<(THREEC * 512 + 255) / 256, 256>>>(Wqkv, Bbk, THREEC * 512);

    // 2) QKV projection -> q/k/v plane blocks
    gemm_blk<true, false><<<dim3(THREEC / 128, MROWS / 128), 256, GEMM_SMEM>>>(
        Ab, Bbk, nullptr, nullptr, qh, ql, kh, kl, vh, vl, THREEC);

    // 3) Causal flash attention -> proj-A blocks (overwrites Ab)
    flash_attn_tc<<<dim3(BH, Tt / 128), 256, FA_SMEM>>>(
        qh, ql, kh, kl, vh, vl, Ab);

    // 4) block-convert Wproj
    convert_blk<<<(Cc * 512 + 255) / 256, 256>>>(Wproj, Bbk, Cc * 512);

    // 5) Output projection (+bias)
    gemm_blk<false, true><<<dim3(Cc / 128, MROWS / 128), 256, GEMM_SMEM>>>(
        Ab, Bbk, bproj, out, nullptr, nullptr, nullptr, nullptr, nullptr,
        nullptr, Cc);
}

// round 9
// speedup vs baseline: 4.8460x; 1.0041x over previous
#include <cuda_runtime.h>
#include <cuda_bf16.h>
#include <math.h>
#include <stdint.h>

// Problem constants
#define Bb    4
#define Tt    2048
#define Cc    1024
#define Hh    16
#define HDd   64
#define MROWS (Bb*Tt)      // 8192
#define THREEC (3*Cc)      // 3072
#define BH    (Bb*Hh)      // 64

// Scratch: block-formatted operands. 16KB block = 128 rows x 128B;
// chunks 0-3 = hi plane (k 0..31), chunks 4-7 = lo plane.
__device__ __nv_bfloat16 g_Ablk[(size_t)MROWS * Cc * 2];    // 32MB
__device__ __nv_bfloat16 g_Bblk[(size_t)THREEC * Cc * 2];   // 12MB (Wqkv)
__device__ __nv_bfloat16 g_Wp[(size_t)Cc * Cc * 2];         // 4MB  (Wproj)
__device__ __nv_bfloat16 g_qh[(size_t)BH * Tt * HDd];
__device__ __nv_bfloat16 g_ql[(size_t)BH * Tt * HDd];
__device__ __nv_bfloat16 g_kh[(size_t)BH * Tt * HDd];
__device__ __nv_bfloat16 g_kl[(size_t)BH * Tt * HDd];
__device__ __nv_bfloat16 g_vh[(size_t)BH * Tt * HDd];
__device__ __nv_bfloat16 g_vl[(size_t)BH * Tt * HDd];

__device__ __forceinline__ uint32_t smem_u32(const void* p) {
    return (uint32_t)__cvta_generic_to_shared(p);
}
__device__ __forceinline__ void mbar_init(uint32_t a, uint32_t cnt) {
    asm volatile("mbarrier.init.shared.b64 [%0], %1;" :: "r"(a), "r"(cnt) : "memory");
}
__device__ __forceinline__ void mbar_expect(uint32_t a, uint32_t tx) {
    asm volatile("mbarrier.arrive.expect_tx.shared.b64 _, [%0], %1;"
                 :: "r"(a), "r"(tx) : "memory");
}
__device__ __forceinline__ void mbar_wait(uint32_t a, uint32_t ph) {
    asm volatile(
        "{\n\t.reg .pred P;\n\t"
        "WL%=:\n\t"
        "mbarrier.try_wait.parity.shared::cta.b64 P, [%0], %1, 0x989680;\n\t"
        "@!P bra WL%=;\n\t}"
        :: "r"(a), "r"(ph) : "memory");
}
__device__ __forceinline__ void bulk_g2s(uint32_t dst, const void* src,
                                         uint32_t bytes, uint32_t mbar) {
    asm volatile(
        "cp.async.bulk.shared::cluster.global.mbarrier::complete_tx::bytes "
        "[%0], [%1], %2, [%3];"
        :: "r"(dst), "l"(src), "r"(bytes), "r"(mbar) : "memory");
}

#define LDSM4(r0, r1, r2, r3, a)                                              \
    asm volatile("ldmatrix.sync.aligned.m8n8.x4.shared.b16 {%0,%1,%2,%3}, [%4];" \
                 : "=r"(r0), "=r"(r1), "=r"(r2), "=r"(r3) : "r"(a))
#define LDSM4T(r0, r1, r2, r3, a)                                             \
    asm volatile("ldmatrix.sync.aligned.m8n8.x4.trans.shared.b16 {%0,%1,%2,%3}, [%4];" \
                 : "=r"(r0), "=r"(r1), "=r"(r2), "=r"(r3) : "r"(a))
#define MMA_BF16(c, a, b0, b1)                                                \
    asm volatile(                                                             \
        "mma.sync.aligned.m16n8k16.row.col.f32.bf16.bf16.f32 "                \
        "{%0,%1,%2,%3},{%4,%5,%6,%7},{%8,%9},{%0,%1,%2,%3};"                  \
        : "+f"((c)[0]), "+f"((c)[1]), "+f"((c)[2]), "+f"((c)[3])              \
        : "r"((a)[0]), "r"((a)[1]), "r"((a)[2]), "r"((a)[3]),                 \
          "r"(b0), "r"(b1))

__device__ __forceinline__ uint32_t swz(int row, int chunk) {
    return (uint32_t)(row * 128 + (((chunk) ^ (row & 7)) << 4));
}
__device__ __forceinline__ void split2(float a, float b, uint32_t& hi, uint32_t& lo) {
    __nv_bfloat16 ha = __float2bfloat16_rn(a);
    __nv_bfloat16 hb = __float2bfloat16_rn(b);
    __nv_bfloat16 la = __float2bfloat16_rn(a - __bfloat162float(ha));
    __nv_bfloat16 lb = __float2bfloat16_rn(b - __bfloat162float(hb));
    hi = ((uint32_t)__bfloat16_as_ushort(hb) << 16) | __bfloat16_as_ushort(ha);
    lo = ((uint32_t)__bfloat16_as_ushort(lb) << 16) | __bfloat16_as_ushort(la);
}

// ---------------------------------------------------------------------------
// Fused convert: x -> Ablk, Wqkv -> Bblk, Wproj -> Wp (all K=1024 rows).
// ---------------------------------------------------------------------------
#define NXP  (MROWS * 512)
#define NQP  (THREEC * 512)
#define NWP  (Cc * 512)

__global__ __launch_bounds__(256)
void convert_all(const float* __restrict__ X, const float* __restrict__ Wq,
                 const float* __restrict__ Wpj,
                 __nv_bfloat16* __restrict__ dstA,
                 __nv_bfloat16* __restrict__ dstB,
                 __nv_bfloat16* __restrict__ dstW)
{
    int e = blockIdx.x * 256 + threadIdx.x;
    const float* src; __nv_bfloat16* dst;
    if (e < NXP)            { src = X;   dst = dstA; }
    else if (e < NXP + NQP) { src = Wq;  dst = dstB; e -= NXP; }
    else if (e < NXP + NQP + NWP) { src = Wpj; dst = dstW; e -= NXP + NQP; }
    else return;
    int r = e >> 9;
    int k = (e & 511) * 2;
    float2 v = *(const float2*)(src + (size_t)r * 1024 + k);
    uint32_t hp, lp;
    split2(v.x, v.y, hp, lp);
    int mt = r >> 7, rr = r & 127, kt = k >> 5, kc = k & 31;
    char* d = (char*)dst + ((size_t)(mt * 32 + kt)) * 16384;
    *(uint32_t*)(d + swz(rr, kc >> 3) + (kc & 7) * 2)       = hp;
    *(uint32_t*)(d + swz(rr, (kc >> 3) + 4) + (kc & 7) * 2) = lp;
}

// ---------------------------------------------------------------------------
// bf16 split-2 tensor GEMM on pre-swizzled blocks. 128x128, BK=32,
// 3-stage bulk pipeline with early prefetch issue, 2 CTAs/SM.
// ---------------------------------------------------------------------------
#define GST 32768
#define GEMM_SMEM (1024 + 3*GST)   // 99328

template<bool QKV, bool HAS_BIAS>
__global__ __launch_bounds__(256, 2)
void gemm_blk(const __nv_bfloat16* __restrict__ Ablk,
              const __nv_bfloat16* __restrict__ Bblk,
              const float* __restrict__ bias, float* __restrict__ Out,
              __nv_bfloat16* Qh, __nv_bfloat16* Ql,
              __nv_bfloat16* Kh, __nv_bfloat16* Kl,
              __nv_bfloat16* Vh, __nv_bfloat16* Vl, int N)
{
    extern __shared__ __align__(1024) char sm[];
    const uint32_t s0 = smem_u32(sm);
    const uint32_t buf0 = s0 + 1024;
    const int tid = threadIdx.x, warp = tid >> 5, lane = tid & 31;
    const int wm = warp & 3, wn = warp >> 2;
    const int grp = lane >> 3, j = lane & 7;
    const int bm = blockIdx.y, bn = blockIdx.x;
    const int NKC = 32;

    if (tid == 0) {
        mbar_init(s0, 1); mbar_init(s0 + 8, 1); mbar_init(s0 + 16, 1);
    }
    __syncthreads();
    if (tid == 0) {
        #pragma unroll
        for (int p = 0; p < 2; p++) {
            uint32_t fb = s0 + p * 8;
            mbar_expect(fb, 2 * 16384);
            bulk_g2s(buf0 + p * GST,
                     (const char*)Ablk + ((size_t)bm * NKC + p) * 16384, 16384, fb);
            bulk_g2s(buf0 + p * GST + 16384,
                     (const char*)Bblk + ((size_t)bn * NKC + p) * 16384, 16384, fb);
        }
    }

    float c[2][8][4];
    #pragma unroll
    for (int a = 0; a < 2; a++)
        #pragma unroll
        for (int b = 0; b < 8; b++)
            #pragma unroll
            for (int q = 0; q < 4; q++) c[a][b][q] = 0.f;

    int stage = 0, ph = 0;
    for (int t = 0; t < NKC; t++) {
        mbar_wait(s0 + stage * 8, ph);
        // early prefetch: stage (t+2)%3 was drained at end of t-1
        if (tid == 0 && t + 2 < NKC) {
            int s2 = stage + 2; if (s2 >= 3) s2 -= 3;
            uint32_t fb = s0 + s2 * 8;
            mbar_expect(fb, 2 * 16384);
            bulk_g2s(buf0 + s2 * GST,
                     (const char*)Ablk + ((size_t)bm * NKC + t + 2) * 16384,
                     16384, fb);
            bulk_g2s(buf0 + s2 * GST + 16384,
                     (const char*)Bblk + ((size_t)bn * NKC + t + 2) * 16384,
                     16384, fb);
        }
        uint32_t sA = buf0 + stage * GST;
        uint32_t sB = sA + 16384;

        #pragma unroll
        for (int ks = 0; ks < 2; ks++) {
            uint32_t ah[2][4], al[2][4];
            #pragma unroll
            for (int mt = 0; mt < 2; mt++) {
                int row = wm * 32 + mt * 16 + ((grp & 1) << 3) + j;
                int ch = ks * 2 + (grp >> 1);
                LDSM4(ah[mt][0], ah[mt][1], ah[mt][2], ah[mt][3], sA + swz(row, ch));
                LDSM4(al[mt][0], al[mt][1], al[mt][2], al[mt][3], sA + swz(row, ch + 4));
            }
            #pragma unroll
            for (int nb = 0; nb < 4; nb++) {
                int rowb = wn * 64 + nb * 16 + ((grp >> 1) << 3) + j;
                int chb = ks * 2 + (grp & 1);
                uint32_t bh[4], bl[4];
                LDSM4(bh[0], bh[1], bh[2], bh[3], sB + swz(rowb, chb));
                LDSM4(bl[0], bl[1], bl[2], bl[3], sB + swz(rowb, chb + 4));
                #pragma unroll
                for (int mt = 0; mt < 2; mt++) {
                    MMA_BF16(c[mt][nb*2],   ah[mt], bh[0], bh[1]);
                    MMA_BF16(c[mt][nb*2],   ah[mt], bl[0], bl[1]);
                    MMA_BF16(c[mt][nb*2],   al[mt], bh[0], bh[1]);
                    MMA_BF16(c[mt][nb*2+1], ah[mt], bh[2], bh[3]);
                    MMA_BF16(c[mt][nb*2+1], ah[mt], bl[2], bl[3]);
                    MMA_BF16(c[mt][nb*2+1], al[mt], bh[2], bh[3]);
                }
            }
        }
        __syncthreads();
        stage++; if (stage == 3) { stage = 0; ph ^= 1; }
    }

    // epilogue
    #pragma unroll
    for (int mt = 0; mt < 2; mt++) {
        int r0 = bm * 128 + wm * 32 + mt * 16 + (lane >> 2);
        #pragma unroll
        for (int ng = 0; ng < 8; ng++) {
            int col = bn * 128 + wn * 64 + ng * 8 + (lane & 3) * 2;
            if (!QKV) {
                float2 v0 = make_float2(c[mt][ng][0], c[mt][ng][1]);
                float2 v1 = make_float2(c[mt][ng][2], c[mt][ng][3]);
                if (HAS_BIAS) {
                    float2 bv = *(const float2*)&bias[col];
                    v0.x += bv.x; v0.y += bv.y;
                    v1.x += bv.x; v1.y += bv.y;
                }
                *(float2*)&Out[(size_t)r0 * N + col] = v0;
                *(float2*)&Out[(size_t)(r0 + 8) * N + col] = v1;
            } else {
                int h  = col / 192;
                int wc = col - h * 192;
                int ty = wc >> 6;
                int d  = wc & 63;
                __nv_bfloat16* Hp = (ty == 0) ? Qh : (ty == 1) ? Kh : Vh;
                __nv_bfloat16* Lp = (ty == 0) ? Ql : (ty == 1) ? Kl : Vl;
                float sc = (ty == 0) ? 0.125f : 1.0f;
                #pragma unroll
                for (int half = 0; half < 2; half++) {
                    int m = r0 + half * 8;
                    int b = m >> 11, tt = m & 2047;
                    int bh2 = b * Hh + h;
                    uint32_t hp, lp;
                    split2(c[mt][ng][half*2] * sc, c[mt][ng][half*2+1] * sc, hp, lp);
                    size_t base; uint32_t off;
                    if (ty == 0) {
                        base = ((size_t)bh2 * 16 + (tt >> 7)) * 16384;
                        off  = swz(tt & 127, d >> 3) + (d & 7) * 2;
                    } else {
                        base = ((size_t)bh2 * 32 + (tt >> 6)) * 8192;
                        off  = swz(tt & 63, d >> 3) + (d & 7) * 2;
                    }
                    *(uint32_t*)((char*)Hp + base + off) = hp;
                    *(uint32_t*)((char*)Lp + base + off) = lp;
                }
            }
        }
    }
}

// ---------------------------------------------------------------------------
// Tensor-core causal flash attention (validated round 7, unchanged).
// ---------------------------------------------------------------------------
#define FA_SMEM (1024 + 32768 + 2*32768)

__global__ __launch_bounds__(256, 2)
void flash_attn_tc(const __nv_bfloat16* __restrict__ qh, const __nv_bfloat16* __restrict__ ql,
                   const __nv_bfloat16* __restrict__ kh, const __nv_bfloat16* __restrict__ kl,
                   const __nv_bfloat16* __restrict__ vh, const __nv_bfloat16* __restrict__ vl,
                   __nv_bfloat16* __restrict__ OA)
{
    extern __shared__ __align__(1024) char sm[];
    const uint32_t s0  = smem_u32(sm);
    const uint32_t QB = s0, FB0 = s0 + 8, FB1 = s0 + 16;
    const uint32_t sQh = s0 + 1024, sQl = sQh + 16384;
    const uint32_t kvb = s0 + 1024 + 32768;

    const int bh = blockIdx.x;
    const int qt = (gridDim.y - 1) - blockIdx.y;
    const int tid = threadIdx.x, w = tid >> 5, lane = tid & 31;
    const int g = lane >> 2, tg = lane & 3;
    const int grp = lane >> 3, j = lane & 7;
    const int nkt = 2 * qt + 2;

    if (tid == 0) { mbar_init(QB, 1); mbar_init(FB0, 1); mbar_init(FB1, 1); }
    __syncthreads();
    if (tid == 0) {
        mbar_expect(QB, 2 * 16384);
        bulk_g2s(sQh, (const char*)qh + ((size_t)bh * 16 + qt) * 16384, 16384, QB);
        bulk_g2s(sQl, (const char*)ql + ((size_t)bh * 16 + qt) * 16384, 16384, QB);
        #pragma unroll
        for (int p = 0; p < 2; p++) {
            uint32_t fb = p ? FB1 : FB0;
            uint32_t dst = kvb + p * 32768;
            size_t kb_ = ((size_t)bh * 32 + p) * 8192;
            mbar_expect(fb, 32768);
            bulk_g2s(dst,         (const char*)kh + kb_, 8192, fb);
            bulk_g2s(dst + 8192,  (const char*)kl + kb_, 8192, fb);
            bulk_g2s(dst + 16384, (const char*)vh + kb_, 8192, fb);
            bulk_g2s(dst + 24576, (const char*)vl + kb_, 8192, fb);
        }
    }
    mbar_wait(QB, 0);

    float o[8][4];
    #pragma unroll
    for (int nb = 0; nb < 8; nb++)
        #pragma unroll
        for (int e = 0; e < 4; e++) o[nb][e] = 0.f;
    float mA = -INFINITY, mB = -INFINITY, lA = 0.f, lB = 0.f;
    const int wrow0 = qt * 128 + w * 16;

    for (int kt = 0; kt < nkt; kt++) {
        mbar_wait((kt & 1) ? FB1 : FB0, (kt >> 1) & 1);
        uint32_t stg = kvb + (kt & 1) * 32768;
        uint32_t sKh = stg, sKl = stg + 8192;
        uint32_t sVh = stg + 16384, sVl = stg + 24576;

        if (kt * 64 <= wrow0 + 15) {
            float s[8][4];
            #pragma unroll
            for (int nb = 0; nb < 8; nb++)
                #pragma unroll
                for (int e = 0; e < 4; e++) s[nb][e] = 0.f;

            #pragma unroll
            for (int kb = 0; kb < 4; kb++) {
                int qrow = w * 16 + ((grp & 1) << 3) + j;
                uint32_t qoff = swz(qrow, kb * 2 + (grp >> 1));
                uint32_t qhf[4], qlf[4];
                LDSM4(qhf[0], qhf[1], qhf[2], qhf[3], sQh + qoff);
                LDSM4(qlf[0], qlf[1], qlf[2], qlf[3], sQl + qoff);
                #pragma unroll
                for (int p = 0; p < 4; p++) {
                    int rowb = p * 16 + ((grp >> 1) << 3) + j;
                    uint32_t off = swz(rowb, kb * 2 + (grp & 1));
                    uint32_t bhr[4], blr[4];
                    LDSM4(bhr[0], bhr[1], bhr[2], bhr[3], sKh + off);
                    LDSM4(blr[0], blr[1], blr[2], blr[3], sKl + off);
                    MMA_BF16(s[p*2],   qhf, bhr[0], bhr[1]);
                    MMA_BF16(s[p*2],   qhf, blr[0], blr[1]);
                    MMA_BF16(s[p*2],   qlf, bhr[0], bhr[1]);
                    MMA_BF16(s[p*2+1], qhf, bhr[2], bhr[3]);
                    MMA_BF16(s[p*2+1], qhf, blr[2], blr[3]);
                    MMA_BF16(s[p*2+1], qlf, bhr[2], bhr[3]);
                }
            }

            if (kt * 64 + 63 > wrow0) {
                int rowA = wrow0 + g, rowB = rowA + 8;
                #pragma unroll
                for (int nb = 0; nb < 8; nb++) {
                    int c0 = kt * 64 + nb * 8 + tg * 2;
                    if (c0 > rowA)     s[nb][0] = -INFINITY;
                    if (c0 + 1 > rowA) s[nb][1] = -INFINITY;
                    if (c0 > rowB)     s[nb][2] = -INFINITY;
                    if (c0 + 1 > rowB) s[nb][3] = -INFINITY;
                }
            }

            float mxA = -INFINITY, mxB = -INFINITY;
            #pragma unroll
            for (int nb = 0; nb < 8; nb++) {
                mxA = fmaxf(mxA, fmaxf(s[nb][0], s[nb][1]));
                mxB = fmaxf(mxB, fmaxf(s[nb][2], s[nb][3]));
            }
            #pragma unroll
            for (int d = 1; d < 4; d <<= 1) {
                mxA = fmaxf(mxA, __shfl_xor_sync(0xffffffffu, mxA, d));
                mxB = fmaxf(mxB, __shfl_xor_sync(0xffffffffu, mxB, d));
            }
            float mAn = fmaxf(mA, mxA), mBn = fmaxf(mB, mxB);
            float aA = __expf(mA - mAn), aB = __expf(mB - mBn);
            float sumA = 0.f, sumB = 0.f;
            #pragma unroll
            for (int nb = 0; nb < 8; nb++) {
                s[nb][0] = __expf(s[nb][0] - mAn); sumA += s[nb][0];
                s[nb][1] = __expf(s[nb][1] - mAn); sumA += s[nb][1];
                s[nb][2] = __expf(s[nb][2] - mBn); sumB += s[nb][2];
                s[nb][3] = __expf(s[nb][3] - mBn); sumB += s[nb][3];
            }
            #pragma unroll
            for (int d = 1; d < 4; d <<= 1) {
                sumA += __shfl_xor_sync(0xffffffffu, sumA, d);
                sumB += __shfl_xor_sync(0xffffffffu, sumB, d);
            }
            lA = lA * aA + sumA; lB = lB * aB + sumB;
            mA = mAn; mB = mBn;
            #pragma unroll
            for (int nb = 0; nb < 8; nb++) {
                o[nb][0] *= aA; o[nb][1] *= aA;
                o[nb][2] *= aB; o[nb][3] *= aB;
            }

            #pragma unroll
            for (int kb = 0; kb < 4; kb++) {
                uint32_t ph2[4], pl2[4];
                split2(s[2*kb][0],   s[2*kb][1],   ph2[0], pl2[0]);
                split2(s[2*kb][2],   s[2*kb][3],   ph2[1], pl2[1]);
                split2(s[2*kb+1][0], s[2*kb+1][1], ph2[2], pl2[2]);
                split2(s[2*kb+1][2], s[2*kb+1][3], ph2[3], pl2[3]);
                #pragma unroll
                for (int p = 0; p < 4; p++) {
                    int keyrow = kb * 16 + ((grp & 1) << 3) + j;
                    uint32_t off = swz(keyrow, p * 2 + (grp >> 1));
                    uint32_t vhr[4], vlr[4];
                    LDSM4T(vhr[0], vhr[1], vhr[2], vhr[3], sVh + off);
                    LDSM4T(vlr[0], vlr[1], vlr[2], vlr[3], sVl + off);
                    MMA_BF16(o[p*2],   ph2, vhr[0], vhr[1]);
                    MMA_BF16(o[p*2],   ph2, vlr[0], vlr[1]);
                    MMA_BF16(o[p*2],   pl2, vhr[0], vhr[1]);
                    MMA_BF16(o[p*2+1], ph2, vhr[2], vhr[3]);
                    MMA_BF16(o[p*2+1], ph2, vlr[2], vlr[3]);
                    MMA_BF16(o[p*2+1], pl2, vhr[2], vhr[3]);
                }
            }
        }
        __syncthreads();
        if (tid == 0 && kt + 2 < nkt) {
            uint32_t fb = (kt & 1) ? FB1 : FB0;
            uint32_t dst = kvb + (kt & 1) * 32768;
            size_t kb_ = ((size_t)bh * 32 + kt + 2) * 8192;
            mbar_expect(fb, 32768);
            bulk_g2s(dst,         (const char*)kh + kb_, 8192, fb);
            bulk_g2s(dst + 8192,  (const char*)kl + kb_, 8192, fb);
            bulk_g2s(dst + 16384, (const char*)vh + kb_, 8192, fb);
            bulk_g2s(dst + 24576, (const char*)vl + kb_, 8192, fb);
        }
    }

    float invA = 1.f / lA, invB = 1.f / lB;
    int b = bh >> 4, h = bh & 15;
    #pragma unroll
    for (int nb = 0; nb < 8; nb++) {
        int col = h * 64 + nb * 8 + tg * 2;
        int ktc = col >> 5, kc = col & 31;
        #pragma unroll
        for (int half = 0; half < 2; half++) {
            int m = b * Tt + qt * 128 + w * 16 + g + half * 8;
            float inv = half ? invB : invA;
            uint32_t hp, lp;
            split2(o[nb][half*2] * inv, o[nb][half*2+1] * inv, hp, lp);
            char* d = (char*)OA + ((size_t)(m >> 7) * 32 + ktc) * 16384;
            *(uint32_t*)(d + swz(m & 127, kc >> 3) + (kc & 7) * 2)       = hp;
            *(uint32_t*)(d + swz(m & 127, (kc >> 3) + 4) + (kc & 7) * 2) = lp;
        }
    }
}

// ---------------------------------------------------------------------------
extern "C" void kernel_launch(void* const* d_in, const int* in_sizes, int n_in,
                              void* d_out, int out_size)
{
    const float* x     = (const float*)d_in[0];
    const float* Wqkv  = (const float*)d_in[1];
    const float* Wproj = (const float*)d_in[2];
    const float* bproj = (const float*)d_in[3];
    float* out = (float*)d_out;

    __nv_bfloat16 *Ab, *Bbk, *Wp, *qh, *ql, *kh, *kl, *vh, *vl;
    cudaGetSymbolAddress((void**)&Ab, g_Ablk);
    cudaGetSymbolAddress((void**)&Bbk, g_Bblk);
    cudaGetSymbolAddress((void**)&Wp, g_Wp);
    cudaGetSymbolAddress((void**)&qh, g_qh);
    cudaGetSymbolAddress((void**)&ql, g_ql);
    cudaGetSymbolAddress((void**)&kh, g_kh);
    cudaGetSymbolAddress((void**)&kl, g_kl);
    cudaGetSymbolAddress((void**)&vh, g_vh);
    cudaGetSymbolAddress((void**)&vl, g_vl);

    cudaFuncSetAttribute((const void*)gemm_blk<true, false>,
                         cudaFuncAttributeMaxDynamicSharedMemorySize, GEMM_SMEM);
    cudaFuncSetAttribute((const void*)gemm_blk<false, true>,
                         cudaFuncAttributeMaxDynamicSharedMemorySize, GEMM_SMEM);
    cudaFuncSetAttribute((const void*)flash_attn_tc,
                         cudaFuncAttributeMaxDynamicSharedMemorySize, FA_SMEM);

    // 1) fused block-convert: x, Wqkv, Wproj
    int total = NXP + NQP + NWP;
    convert_all<<<(total + 255) / 256, 256>>>(x, Wqkv, Wproj, Ab, Bbk, Wp);

    // 2) QKV projection -> q/k/v plane blocks
    gemm_blk<true, false><<<dim3(THREEC / 128, MROWS / 128), 256, GEMM_SMEM>>>(
        Ab, Bbk, nullptr, nullptr, qh, ql, kh, kl, vh, vl, THREEC);

    // 3) Causal flash attention -> proj-A blocks (overwrites Ab)
    flash_attn_tc<<<dim3(BH, Tt / 128), 256, FA_SMEM>>>(
        qh, ql, kh, kl, vh, vl, Ab);

    // 4) Output projection (+bias)
    gemm_blk<false, true><<<dim3(Cc / 128, MROWS / 128), 256, GEMM_SMEM>>>(
        Ab, Wp, bproj, out, nullptr, nullptr, nullptr, nullptr, nullptr,
        nullptr, Cc);
}

// round 10
// speedup vs baseline: 4.9009x; 1.0113x over previous
#include <cuda_runtime.h>
#include <cuda_bf16.h>
#include <math.h>
#include <stdint.h>

// Problem constants
#define Bb    4
#define Tt    2048
#define Cc    1024
#define Hh    16
#define HDd   64
#define MROWS (Bb*Tt)      // 8192
#define THREEC (3*Cc)      // 3072
#define BH    (Bb*Hh)      // 64

// Scratch: block-formatted operands. 16KB block = 128 rows x 128B;
// chunks 0-3 = hi plane (k 0..31), chunks 4-7 = lo plane.
__device__ __nv_bfloat16 g_Ablk[(size_t)MROWS * Cc * 2];    // 32MB
__device__ __nv_bfloat16 g_Bblk[(size_t)THREEC * Cc * 2];   // 12MB (Wqkv)
__device__ __nv_bfloat16 g_Wp[(size_t)Cc * Cc * 2];         // 4MB  (Wproj)
__device__ __nv_bfloat16 g_qh[(size_t)BH * Tt * HDd];
__device__ __nv_bfloat16 g_ql[(size_t)BH * Tt * HDd];
__device__ __nv_bfloat16 g_kh[(size_t)BH * Tt * HDd];
__device__ __nv_bfloat16 g_kl[(size_t)BH * Tt * HDd];
__device__ __nv_bfloat16 g_vh[(size_t)BH * Tt * HDd];
__device__ __nv_bfloat16 g_vl[(size_t)BH * Tt * HDd];

__device__ __forceinline__ uint32_t smem_u32(const void* p) {
    return (uint32_t)__cvta_generic_to_shared(p);
}
__device__ __forceinline__ void mbar_init(uint32_t a, uint32_t cnt) {
    asm volatile("mbarrier.init.shared.b64 [%0], %1;" :: "r"(a), "r"(cnt) : "memory");
}
__device__ __forceinline__ void mbar_expect(uint32_t a, uint32_t tx) {
    asm volatile("mbarrier.arrive.expect_tx.shared.b64 _, [%0], %1;"
                 :: "r"(a), "r"(tx) : "memory");
}
__device__ __forceinline__ void mbar_arrive(uint32_t a) {
    asm volatile("mbarrier.arrive.shared.b64 _, [%0];" :: "r"(a) : "memory");
}
__device__ __forceinline__ void mbar_wait(uint32_t a, uint32_t ph) {
    asm volatile(
        "{\n\t.reg .pred P;\n\t"
        "WL%=:\n\t"
        "mbarrier.try_wait.parity.shared::cta.b64 P, [%0], %1, 0x989680;\n\t"
        "@!P bra WL%=;\n\t}"
        :: "r"(a), "r"(ph) : "memory");
}
__device__ __forceinline__ void bulk_g2s(uint32_t dst, const void* src,
                                         uint32_t bytes, uint32_t mbar) {
    asm volatile(
        "cp.async.bulk.shared::cluster.global.mbarrier::complete_tx::bytes "
        "[%0], [%1], %2, [%3];"
        :: "r"(dst), "l"(src), "r"(bytes), "r"(mbar) : "memory");
}

#define LDSM4(r0, r1, r2, r3, a)                                              \
    asm volatile("ldmatrix.sync.aligned.m8n8.x4.shared.b16 {%0,%1,%2,%3}, [%4];" \
                 : "=r"(r0), "=r"(r1), "=r"(r2), "=r"(r3) : "r"(a))
#define LDSM4T(r0, r1, r2, r3, a)                                             \
    asm volatile("ldmatrix.sync.aligned.m8n8.x4.trans.shared.b16 {%0,%1,%2,%3}, [%4];" \
                 : "=r"(r0), "=r"(r1), "=r"(r2), "=r"(r3) : "r"(a))
#define MMA_BF16(c, a, b0, b1)                                                \
    asm volatile(                                                             \
        "mma.sync.aligned.m16n8k16.row.col.f32.bf16.bf16.f32 "                \
        "{%0,%1,%2,%3},{%4,%5,%6,%7},{%8,%9},{%0,%1,%2,%3};"                  \
        : "+f"((c)[0]), "+f"((c)[1]), "+f"((c)[2]), "+f"((c)[3])              \
        : "r"((a)[0]), "r"((a)[1]), "r"((a)[2]), "r"((a)[3]),                 \
          "r"(b0), "r"(b1))

__device__ __forceinline__ uint32_t swz(int row, int chunk) {
    return (uint32_t)(row * 128 + (((chunk) ^ (row & 7)) << 4));
}
__device__ __forceinline__ void split2(float a, float b, uint32_t& hi, uint32_t& lo) {
    __nv_bfloat16 ha = __float2bfloat16_rn(a);
    __nv_bfloat16 hb = __float2bfloat16_rn(b);
    __nv_bfloat16 la = __float2bfloat16_rn(a - __bfloat162float(ha));
    __nv_bfloat16 lb = __float2bfloat16_rn(b - __bfloat162float(hb));
    hi = ((uint32_t)__bfloat16_as_ushort(hb) << 16) | __bfloat16_as_ushort(ha);
    lo = ((uint32_t)__bfloat16_as_ushort(lb) << 16) | __bfloat16_as_ushort(la);
}

// ---------------------------------------------------------------------------
// Fused convert: x -> Ablk, Wqkv -> Bblk, Wproj -> Wp (all K=1024 rows).
// ---------------------------------------------------------------------------
#define NXP  (MROWS * 512)
#define NQP  (THREEC * 512)
#define NWP  (Cc * 512)

__global__ __launch_bounds__(256)
void convert_all(const float* __restrict__ X, const float* __restrict__ Wq,
                 const float* __restrict__ Wpj,
                 __nv_bfloat16* __restrict__ dstA,
                 __nv_bfloat16* __restrict__ dstB,
                 __nv_bfloat16* __restrict__ dstW)
{
    int e = blockIdx.x * 256 + threadIdx.x;
    const float* src; __nv_bfloat16* dst;
    if (e < NXP)            { src = X;   dst = dstA; }
    else if (e < NXP + NQP) { src = Wq;  dst = dstB; e -= NXP; }
    else if (e < NXP + NQP + NWP) { src = Wpj; dst = dstW; e -= NXP + NQP; }
    else return;
    int r = e >> 9;
    int k = (e & 511) * 2;
    float2 v = *(const float2*)(src + (size_t)r * 1024 + k);
    uint32_t hp, lp;
    split2(v.x, v.y, hp, lp);
    int mt = r >> 7, rr = r & 127, kt = k >> 5, kc = k & 31;
    char* d = (char*)dst + ((size_t)(mt * 32 + kt)) * 16384;
    *(uint32_t*)(d + swz(rr, kc >> 3) + (kc & 7) * 2)       = hp;
    *(uint32_t*)(d + swz(rr, (kc >> 3) + 4) + (kc & 7) * 2) = lp;
}

// ---------------------------------------------------------------------------
// bf16 split-2 tensor GEMM on pre-swizzled blocks. 128x128, BK=32,
// 3-stage bulk pipeline, mbarrier producer/consumer (NO in-loop syncthreads),
// 2 CTAs/SM.
// ---------------------------------------------------------------------------
#define GST 32768
#define GEMM_SMEM (1024 + 3*GST)   // 99328

template<bool QKV, bool HAS_BIAS>
__global__ __launch_bounds__(256, 2)
void gemm_blk(const __nv_bfloat16* __restrict__ Ablk,
              const __nv_bfloat16* __restrict__ Bblk,
              const float* __restrict__ bias, float* __restrict__ Out,
              __nv_bfloat16* Qh, __nv_bfloat16* Ql,
              __nv_bfloat16* Kh, __nv_bfloat16* Kl,
              __nv_bfloat16* Vh, __nv_bfloat16* Vl, int N)
{
    extern __shared__ __align__(1024) char sm[];
    const uint32_t s0 = smem_u32(sm);          // full[3] @ +0,8,16
    const uint32_t e0 = s0 + 24;               // empty[3] @ +24,32,40
    const uint32_t buf0 = s0 + 1024;
    const int tid = threadIdx.x, warp = tid >> 5, lane = tid & 31;
    const int wm = warp & 3, wn = warp >> 2;
    const int grp = lane >> 3, j = lane & 7;
    const int bm = blockIdx.y, bn = blockIdx.x;
    const int NKC = 32;

    if (tid == 0) {
        mbar_init(s0, 1); mbar_init(s0 + 8, 1); mbar_init(s0 + 16, 1);
        mbar_init(e0, 8); mbar_init(e0 + 8, 8); mbar_init(e0 + 16, 8);
    }
    __syncthreads();
    if (tid == 0) {
        #pragma unroll
        for (int p = 0; p < 2; p++) {
            uint32_t fb = s0 + p * 8;
            mbar_expect(fb, 2 * 16384);
            bulk_g2s(buf0 + p * GST,
                     (const char*)Ablk + ((size_t)bm * NKC + p) * 16384, 16384, fb);
            bulk_g2s(buf0 + p * GST + 16384,
                     (const char*)Bblk + ((size_t)bn * NKC + p) * 16384, 16384, fb);
        }
    }

    float c[2][8][4];
    #pragma unroll
    for (int a = 0; a < 2; a++)
        #pragma unroll
        for (int b = 0; b < 8; b++)
            #pragma unroll
            for (int q = 0; q < 4; q++) c[a][b][q] = 0.f;

    int stage = 0, ph = 0;
    for (int t = 0; t < NKC; t++) {
        // producer: refill stage (t+2)%3 once all warps emptied it
        if (tid == 0 && t + 2 < NKC) {
            int s2 = stage + 2; if (s2 >= 3) s2 -= 3;
            int f = (t + 2) / 3;            // fill index of that stage
            if (f >= 1) mbar_wait(e0 + s2 * 8, (f - 1) & 1);
            uint32_t fb = s0 + s2 * 8;
            mbar_expect(fb, 2 * 16384);
            bulk_g2s(buf0 + s2 * GST,
                     (const char*)Ablk + ((size_t)bm * NKC + t + 2) * 16384,
                     16384, fb);
            bulk_g2s(buf0 + s2 * GST + 16384,
                     (const char*)Bblk + ((size_t)bn * NKC + t + 2) * 16384,
                     16384, fb);
        }
        mbar_wait(s0 + stage * 8, ph);
        uint32_t sA = buf0 + stage * GST;
        uint32_t sB = sA + 16384;

        #pragma unroll
        for (int ks = 0; ks < 2; ks++) {
            uint32_t ah[2][4], al[2][4];
            #pragma unroll
            for (int mt = 0; mt < 2; mt++) {
                int row = wm * 32 + mt * 16 + ((grp & 1) << 3) + j;
                int ch = ks * 2 + (grp >> 1);
                LDSM4(ah[mt][0], ah[mt][1], ah[mt][2], ah[mt][3], sA + swz(row, ch));
                LDSM4(al[mt][0], al[mt][1], al[mt][2], al[mt][3], sA + swz(row, ch + 4));
            }
            #pragma unroll
            for (int nb = 0; nb < 4; nb++) {
                int rowb = wn * 64 + nb * 16 + ((grp >> 1) << 3) + j;
                int chb = ks * 2 + (grp & 1);
                uint32_t bh[4], bl[4];
                LDSM4(bh[0], bh[1], bh[2], bh[3], sB + swz(rowb, chb));
                LDSM4(bl[0], bl[1], bl[2], bl[3], sB + swz(rowb, chb + 4));
                #pragma unroll
                for (int mt = 0; mt < 2; mt++) {
                    MMA_BF16(c[mt][nb*2],   ah[mt], bh[0], bh[1]);
                    MMA_BF16(c[mt][nb*2],   ah[mt], bl[0], bl[1]);
                    MMA_BF16(c[mt][nb*2],   al[mt], bh[0], bh[1]);
                    MMA_BF16(c[mt][nb*2+1], ah[mt], bh[2], bh[3]);
                    MMA_BF16(c[mt][nb*2+1], ah[mt], bl[2], bl[3]);
                    MMA_BF16(c[mt][nb*2+1], al[mt], bh[2], bh[3]);
                }
            }
        }
        if (lane == 0) mbar_arrive(e0 + stage * 8);   // warp done with stage
        stage++; if (stage == 3) { stage = 0; ph ^= 1; }
    }

    // epilogue
    #pragma unroll
    for (int mt = 0; mt < 2; mt++) {
        int r0 = bm * 128 + wm * 32 + mt * 16 + (lane >> 2);
        #pragma unroll
        for (int ng = 0; ng < 8; ng++) {
            int col = bn * 128 + wn * 64 + ng * 8 + (lane & 3) * 2;
            if (!QKV) {
                float2 v0 = make_float2(c[mt][ng][0], c[mt][ng][1]);
                float2 v1 = make_float2(c[mt][ng][2], c[mt][ng][3]);
                if (HAS_BIAS) {
                    float2 bv = *(const float2*)&bias[col];
                    v0.x += bv.x; v0.y += bv.y;
                    v1.x += bv.x; v1.y += bv.y;
                }
                *(float2*)&Out[(size_t)r0 * N + col] = v0;
                *(float2*)&Out[(size_t)(r0 + 8) * N + col] = v1;
            } else {
                int h  = col / 192;
                int wc = col - h * 192;
                int ty = wc >> 6;
                int d  = wc & 63;
                __nv_bfloat16* Hp = (ty == 0) ? Qh : (ty == 1) ? Kh : Vh;
                __nv_bfloat16* Lp = (ty == 0) ? Ql : (ty == 1) ? Kl : Vl;
                float sc = (ty == 0) ? 0.125f : 1.0f;
                #pragma unroll
                for (int half = 0; half < 2; half++) {
                    int m = r0 + half * 8;
                    int b = m >> 11, tt = m & 2047;
                    int bh2 = b * Hh + h;
                    uint32_t hp, lp;
                    split2(c[mt][ng][half*2] * sc, c[mt][ng][half*2+1] * sc, hp, lp);
                    size_t base; uint32_t off;
                    if (ty == 0) {
                        base = ((size_t)bh2 * 16 + (tt >> 7)) * 16384;
                        off  = swz(tt & 127, d >> 3) + (d & 7) * 2;
                    } else {
                        base = ((size_t)bh2 * 32 + (tt >> 6)) * 8192;
                        off  = swz(tt & 63, d >> 3) + (d & 7) * 2;
                    }
                    *(uint32_t*)((char*)Hp + base + off) = hp;
                    *(uint32_t*)((char*)Lp + base + off) = lp;
                }
            }
        }
    }
}

// ---------------------------------------------------------------------------
// Tensor-core causal flash attention; mbarrier producer/consumer KV pipeline
// (no in-loop syncthreads). smem: hdr 1KB + Q 32KB + 2x32KB = 97KB, 2 CTAs/SM.
// ---------------------------------------------------------------------------
#define FA_SMEM (1024 + 32768 + 2*32768)

__global__ __launch_bounds__(256, 2)
void flash_attn_tc(const __nv_bfloat16* __restrict__ qh, const __nv_bfloat16* __restrict__ ql,
                   const __nv_bfloat16* __restrict__ kh, const __nv_bfloat16* __restrict__ kl,
                   const __nv_bfloat16* __restrict__ vh, const __nv_bfloat16* __restrict__ vl,
                   __nv_bfloat16* __restrict__ OA)
{
    extern __shared__ __align__(1024) char sm[];
    const uint32_t s0  = smem_u32(sm);
    const uint32_t QB = s0, FB0 = s0 + 8, FB1 = s0 + 16;
    const uint32_t EB0 = s0 + 24, EB1 = s0 + 32;
    const uint32_t sQh = s0 + 1024, sQl = sQh + 16384;
    const uint32_t kvb = s0 + 1024 + 32768;

    const int bh = blockIdx.x;
    const int qt = (gridDim.y - 1) - blockIdx.y;
    const int tid = threadIdx.x, w = tid >> 5, lane = tid & 31;
    const int g = lane >> 2, tg = lane & 3;
    const int grp = lane >> 3, j = lane & 7;
    const int nkt = 2 * qt + 2;

    if (tid == 0) {
        mbar_init(QB, 1); mbar_init(FB0, 1); mbar_init(FB1, 1);
        mbar_init(EB0, 8); mbar_init(EB1, 8);
    }
    __syncthreads();
    if (tid == 0) {
        mbar_expect(QB, 2 * 16384);
        bulk_g2s(sQh, (const char*)qh + ((size_t)bh * 16 + qt) * 16384, 16384, QB);
        bulk_g2s(sQl, (const char*)ql + ((size_t)bh * 16 + qt) * 16384, 16384, QB);
        #pragma unroll
        for (int p = 0; p < 2; p++) {
            uint32_t fb = p ? FB1 : FB0;
            uint32_t dst = kvb + p * 32768;
            size_t kb_ = ((size_t)bh * 32 + p) * 8192;
            mbar_expect(fb, 32768);
            bulk_g2s(dst,         (const char*)kh + kb_, 8192, fb);
            bulk_g2s(dst + 8192,  (const char*)kl + kb_, 8192, fb);
            bulk_g2s(dst + 16384, (const char*)vh + kb_, 8192, fb);
            bulk_g2s(dst + 24576, (const char*)vl + kb_, 8192, fb);
        }
    }
    mbar_wait(QB, 0);

    float o[8][4];
    #pragma unroll
    for (int nb = 0; nb < 8; nb++)
        #pragma unroll
        for (int e = 0; e < 4; e++) o[nb][e] = 0.f;
    float mA = -INFINITY, mB = -INFINITY, lA = 0.f, lB = 0.f;
    const int wrow0 = qt * 128 + w * 16;

    for (int kt = 0; kt < nkt; kt++) {
        mbar_wait((kt & 1) ? FB1 : FB0, (kt >> 1) & 1);
        uint32_t stg = kvb + (kt & 1) * 32768;
        uint32_t sKh = stg, sKl = stg + 8192;
        uint32_t sVh = stg + 16384, sVl = stg + 24576;

        if (kt * 64 <= wrow0 + 15) {
            float s[8][4];
            #pragma unroll
            for (int nb = 0; nb < 8; nb++)
                #pragma unroll
                for (int e = 0; e < 4; e++) s[nb][e] = 0.f;

            #pragma unroll
            for (int kb = 0; kb < 4; kb++) {
                int qrow = w * 16 + ((grp & 1) << 3) + j;
                uint32_t qoff = swz(qrow, kb * 2 + (grp >> 1));
                uint32_t qhf[4], qlf[4];
                LDSM4(qhf[0], qhf[1], qhf[2], qhf[3], sQh + qoff);
                LDSM4(qlf[0], qlf[1], qlf[2], qlf[3], sQl + qoff);
                #pragma unroll
                for (int p = 0; p < 4; p++) {
                    int rowb = p * 16 + ((grp >> 1) << 3) + j;
                    uint32_t off = swz(rowb, kb * 2 + (grp & 1));
                    uint32_t bhr[4], blr[4];
                    LDSM4(bhr[0], bhr[1], bhr[2], bhr[3], sKh + off);
                    LDSM4(blr[0], blr[1], blr[2], blr[3], sKl + off);
                    MMA_BF16(s[p*2],   qhf, bhr[0], bhr[1]);
                    MMA_BF16(s[p*2],   qhf, blr[0], blr[1]);
                    MMA_BF16(s[p*2],   qlf, bhr[0], bhr[1]);
                    MMA_BF16(s[p*2+1], qhf, bhr[2], bhr[3]);
                    MMA_BF16(s[p*2+1], qhf, blr[2], blr[3]);
                    MMA_BF16(s[p*2+1], qlf, bhr[2], bhr[3]);
                }
            }

            if (kt * 64 + 63 > wrow0) {
                int rowA = wrow0 + g, rowB = rowA + 8;
                #pragma unroll
                for (int nb = 0; nb < 8; nb++) {
                    int c0 = kt * 64 + nb * 8 + tg * 2;
                    if (c0 > rowA)     s[nb][0] = -INFINITY;
                    if (c0 + 1 > rowA) s[nb][1] = -INFINITY;
                    if (c0 > rowB)     s[nb][2] = -INFINITY;
                    if (c0 + 1 > rowB) s[nb][3] = -INFINITY;
                }
            }

            float mxA = -INFINITY, mxB = -INFINITY;
            #pragma unroll
            for (int nb = 0; nb < 8; nb++) {
                mxA = fmaxf(mxA, fmaxf(s[nb][0], s[nb][1]));
                mxB = fmaxf(mxB, fmaxf(s[nb][2], s[nb][3]));
            }
            #pragma unroll
            for (int d = 1; d < 4; d <<= 1) {
                mxA = fmaxf(mxA, __shfl_xor_sync(0xffffffffu, mxA, d));
                mxB = fmaxf(mxB, __shfl_xor_sync(0xffffffffu, mxB, d));
            }
            float mAn = fmaxf(mA, mxA), mBn = fmaxf(mB, mxB);
            float aA = __expf(mA - mAn), aB = __expf(mB - mBn);
            float sumA = 0.f, sumB = 0.f;
            #pragma unroll
            for (int nb = 0; nb < 8; nb++) {
                s[nb][0] = __expf(s[nb][0] - mAn); sumA += s[nb][0];
                s[nb][1] = __expf(s[nb][1] - mAn); sumA += s[nb][1];
                s[nb][2] = __expf(s[nb][2] - mBn); sumB += s[nb][2];
                s[nb][3] = __expf(s[nb][3] - mBn); sumB += s[nb][3];
            }
            #pragma unroll
            for (int d = 1; d < 4; d <<= 1) {
                sumA += __shfl_xor_sync(0xffffffffu, sumA, d);
                sumB += __shfl_xor_sync(0xffffffffu, sumB, d);
            }
            lA = lA * aA + sumA; lB = lB * aB + sumB;
            mA = mAn; mB = mBn;
            #pragma unroll
            for (int nb = 0; nb < 8; nb++) {
                o[nb][0] *= aA; o[nb][1] *= aA;
                o[nb][2] *= aB; o[nb][3] *= aB;
            }

            #pragma unroll
            for (int kb = 0; kb < 4; kb++) {
                uint32_t ph2[4], pl2[4];
                split2(s[2*kb][0],   s[2*kb][1],   ph2[0], pl2[0]);
                split2(s[2*kb][2],   s[2*kb][3],   ph2[1], pl2[1]);
                split2(s[2*kb+1][0], s[2*kb+1][1], ph2[2], pl2[2]);
                split2(s[2*kb+1][2], s[2*kb+1][3], ph2[3], pl2[3]);
                #pragma unroll
                for (int p = 0; p < 4; p++) {
                    int keyrow = kb * 16 + ((grp & 1) << 3) + j;
                    uint32_t off = swz(keyrow, p * 2 + (grp >> 1));
                    uint32_t vhr[4], vlr[4];
                    LDSM4T(vhr[0], vhr[1], vhr[2], vhr[3], sVh + off);
                    LDSM4T(vlr[0], vlr[1], vlr[2], vlr[3], sVl + off);
                    MMA_BF16(o[p*2],   ph2, vhr[0], vhr[1]);
                    MMA_BF16(o[p*2],   ph2, vlr[0], vlr[1]);
                    MMA_BF16(o[p*2],   pl2, vhr[0], vhr[1]);
                    MMA_BF16(o[p*2+1], ph2, vhr[2], vhr[3]);
                    MMA_BF16(o[p*2+1], ph2, vlr[2], vlr[3]);
                    MMA_BF16(o[p*2+1], pl2, vhr[2], vhr[3]);
                }
            }
        }
        // warp done with this KV stage
        if (lane == 0) mbar_arrive((kt & 1) ? EB1 : EB0);
        // producer: refill this stage for kt+2 once ALL warps are done with kt
        if (tid == 0 && kt + 2 < nkt) {
            mbar_wait((kt & 1) ? EB1 : EB0, (kt >> 1) & 1);
            uint32_t fb = (kt & 1) ? FB1 : FB0;
            uint32_t dst = kvb + (kt & 1) * 32768;
            size_t kb_ = ((size_t)bh * 32 + kt + 2) * 8192;
            mbar_expect(fb, 32768);
            bulk_g2s(dst,         (const char*)kh + kb_, 8192, fb);
            bulk_g2s(dst + 8192,  (const char*)kl + kb_, 8192, fb);
            bulk_g2s(dst + 16384, (const char*)vh + kb_, 8192, fb);
            bulk_g2s(dst + 24576, (const char*)vl + kb_, 8192, fb);
        }
    }

    float invA = 1.f / lA, invB = 1.f / lB;
    int b = bh >> 4, h = bh & 15;
    #pragma unroll
    for (int nb = 0; nb < 8; nb++) {
        int col = h * 64 + nb * 8 + tg * 2;
        int ktc = col >> 5, kc = col & 31;
        #pragma unroll
        for (int half = 0; half < 2; half++) {
            int m = b * Tt + qt * 128 + w * 16 + g + half * 8;
            float inv = half ? invB : invA;
            uint32_t hp, lp;
            split2(o[nb][half*2] * inv, o[nb][half*2+1] * inv, hp, lp);
            char* d = (char*)OA + ((size_t)(m >> 7) * 32 + ktc) * 16384;
            *(uint32_t*)(d + swz(m & 127, kc >> 3) + (kc & 7) * 2)       = hp;
            *(uint32_t*)(d + swz(m & 127, (kc >> 3) + 4) + (kc & 7) * 2) = lp;
        }
    }
}

// ---------------------------------------------------------------------------
extern "C" void kernel_launch(void* const* d_in, const int* in_sizes, int n_in,
                              void* d_out, int out_size)
{
    const float* x     = (const float*)d_in[0];
    const float* Wqkv  = (const float*)d_in[1];
    const float* Wproj = (const float*)d_in[2];
    const float* bproj = (const float*)d_in[3];
    float* out = (float*)d_out;

    __nv_bfloat16 *Ab, *Bbk, *Wp, *qh, *ql, *kh, *kl, *vh, *vl;
    cudaGetSymbolAddress((void**)&Ab, g_Ablk);
    cudaGetSymbolAddress((void**)&Bbk, g_Bblk);
    cudaGetSymbolAddress((void**)&Wp, g_Wp);
    cudaGetSymbolAddress((void**)&qh, g_qh);
    cudaGetSymbolAddress((void**)&ql, g_ql);
    cudaGetSymbolAddress((void**)&kh, g_kh);
    cudaGetSymbolAddress((void**)&kl, g_kl);
    cudaGetSymbolAddress((void**)&vh, g_vh);
    cudaGetSymbolAddress((void**)&vl, g_vl);

    cudaFuncSetAttribute((const void*)gemm_blk<true, false>,
                         cudaFuncAttributeMaxDynamicSharedMemorySize, GEMM_SMEM);
    cudaFuncSetAttribute((const void*)gemm_blk<false, true>,
                         cudaFuncAttributeMaxDynamicSharedMemorySize, GEMM_SMEM);
    cudaFuncSetAttribute((const void*)flash_attn_tc,
                         cudaFuncAttributeMaxDynamicSharedMemorySize, FA_SMEM);

    // 1) fused block-convert: x, Wqkv, Wproj
    int total = NXP + NQP + NWP;
    convert_all<<<(total + 255) / 256, 256>>>(x, Wqkv, Wproj, Ab, Bbk, Wp);

    // 2) QKV projection -> q/k/v plane blocks
    gemm_blk<true, false><<<dim3(THREEC / 128, MROWS / 128), 256, GEMM_SMEM>>>(
        Ab, Bbk, nullptr, nullptr, qh, ql, kh, kl, vh, vl, THREEC);

    // 3) Causal flash attention -> proj-A blocks (overwrites Ab)
    flash_attn_tc<<<dim3(BH, Tt / 128), 256, FA_SMEM>>>(
        qh, ql, kh, kl, vh, vl, Ab);

    // 4) Output projection (+bias)
    gemm_blk<false, true><<<dim3(Cc / 128, MROWS / 128), 256, GEMM_SMEM>>>(
        Ab, Wp, bproj, out, nullptr, nullptr, nullptr, nullptr, nullptr,
        nullptr, Cc);
}